// round 1
// baseline (speedup 1.0000x reference)
#include <cuda_runtime.h>
#include <cuda_fp16.h>
#include <stdint.h>

// SCSWMHSA: 1024 independent (window, head) attention problems, L=256, D=32,
// fused with depthwise-3x3 LePE conv. fp16 MMA (m16n8k16) with fp32 accum.
//
// smem layout (bytes):
//   sQ   half[256][40]   @      0 .. 20480   (Q * SCALE, fp16)
//   sK   half[256][40]   @  20480 .. 40960
//   sV   half[256][40]   @  40960 .. 61440
//   sV32 float[256][33]  @  61440 .. 95232   (fp32 V for LePE conv)
//   sW   float[32][9]    @  95232 .. 96384
//   sB   float[32]       @  96384 .. 96512
#define SMEM_BYTES 96512

__device__ __forceinline__ void ldm4(uint32_t a, uint32_t& r0, uint32_t& r1,
                                     uint32_t& r2, uint32_t& r3) {
    asm volatile("ldmatrix.sync.aligned.m8n8.x4.shared.b16 {%0,%1,%2,%3}, [%4];"
                 : "=r"(r0), "=r"(r1), "=r"(r2), "=r"(r3) : "r"(a));
}
__device__ __forceinline__ void ldm4t(uint32_t a, uint32_t& r0, uint32_t& r1,
                                      uint32_t& r2, uint32_t& r3) {
    asm volatile("ldmatrix.sync.aligned.m8n8.x4.trans.shared.b16 {%0,%1,%2,%3}, [%4];"
                 : "=r"(r0), "=r"(r1), "=r"(r2), "=r"(r3) : "r"(a));
}
__device__ __forceinline__ void mma16816(float* c,
                                         uint32_t a0, uint32_t a1, uint32_t a2, uint32_t a3,
                                         uint32_t b0, uint32_t b1) {
    asm volatile("mma.sync.aligned.m16n8k16.row.col.f32.f16.f16.f32 "
                 "{%0,%1,%2,%3},{%4,%5,%6,%7},{%8,%9},{%0,%1,%2,%3};"
                 : "+f"(c[0]), "+f"(c[1]), "+f"(c[2]), "+f"(c[3])
                 : "r"(a0), "r"(a1), "r"(a2), "r"(a3), "r"(b0), "r"(b1));
}
__device__ __forceinline__ uint32_t packh2(float a, float b) {
    __half2 h = __floats2half2_rn(a, b);
    return *reinterpret_cast<uint32_t*>(&h);
}

__global__ void __launch_bounds__(128)
scswmhsa_kernel(const float* __restrict__ temp,
                const float* __restrict__ wgt,
                const float* __restrict__ bias,
                float* __restrict__ out)
{
    const int bid  = blockIdx.x;
    const int b    = bid >> 7;          // batch
    const int head = (bid >> 4) & 7;    // head
    const int ww   = bid & 15;          // window column index

    const int tid  = threadIdx.x;
    const int lane = tid & 31;
    const int wid  = tid >> 5;

    extern __shared__ char smem[];
    __half* sQ   = reinterpret_cast<__half*>(smem);            // [256][40]
    __half* sK   = reinterpret_cast<__half*>(smem + 20480);    // [256][40]
    __half* sV   = reinterpret_cast<__half*>(smem + 40960);    // [256][40]
    float*  sV32 = reinterpret_cast<float*>(smem + 61440);     // [256][33]
    float*  sW   = reinterpret_cast<float*>(smem + 95232);     // [32][9]
    float*  sB   = reinterpret_cast<float*>(smem + 96384);     // [32]

    const int cbase = head * 32;

    // depthwise conv weights / bias for this head's 32 channels
    for (int i = tid; i < 288; i += 128) sW[i] = wgt[cbase * 9 + i];
    if (tid < 32) sB[tid] = bias[cbase + tid];

    // plane bases inside temp (B, 3, C, 64, 64)
    const size_t pq = ((size_t)(b * 3 + 0) * 256 + cbase) * 4096;
    const size_t pk = ((size_t)(b * 3 + 1) * 256 + cbase) * 4096;
    const size_t pv = ((size_t)(b * 3 + 2) * 256 + cbase) * 4096;
    const float scale = 0.17677669529663687f;  // 32^-0.5

    // Gather window: token t = h_sp*4 + w_sp ; h = t>>2 ; w = (t&3)*16 + ww
#pragma unroll 4
    for (int i = tid; i < 8192; i += 128) {
        const int t = i >> 5;
        const int d = i & 31;
        const int off = d * 4096 + (t >> 2) * 64 + ((t & 3) << 4) + ww;
        const float q = temp[pq + off];
        const float k = temp[pk + off];
        const float v = temp[pv + off];
        sQ[t * 40 + d]  = __float2half_rn(q * scale);
        sK[t * 40 + d]  = __float2half_rn(k);
        sV[t * 40 + d]  = __float2half_rn(v);
        sV32[t * 33 + d] = v;
    }
    __syncthreads();

    const uint32_t qb = (uint32_t)__cvta_generic_to_shared(sQ);
    const uint32_t kb = (uint32_t)__cvta_generic_to_shared(sK);
    const uint32_t vb = (uint32_t)__cvta_generic_to_shared(sV);

    const int lrow = lane & 15;
    const int lcol = (lane >> 4) << 3;
    const int g    = lane >> 2;         // row within 8-row fragment group
    const int tg2  = (lane & 3) << 1;   // col pair base within fragment

    const size_t outBase = ((size_t)b * 256 + cbase) * 4096 + ww;

    // Each warp handles 4 strips of 16 query rows: full 16x256 S in registers.
    for (int s = 0; s < 4; ++s) {
        const int r0 = (s * 4 + wid) * 16;

        // Q A-fragments for both k-steps (d 0..15, 16..31)
        uint32_t aq0[4], aq1[4];
        ldm4(qb + (uint32_t)(((r0 + lrow) * 40 + lcol) * 2),      aq0[0], aq0[1], aq0[2], aq0[3]);
        ldm4(qb + (uint32_t)(((r0 + lrow) * 40 + 16 + lcol) * 2), aq1[0], aq1[1], aq1[2], aq1[3]);

        float c[32][4];
#pragma unroll
        for (int nt = 0; nt < 32; ++nt) {
            c[nt][0] = 0.f; c[nt][1] = 0.f; c[nt][2] = 0.f; c[nt][3] = 0.f;
        }

        // S = (Q*scale) K^T : K loaded non-trans (B col-major == K row-major)
#pragma unroll
        for (int n2 = 0; n2 < 16; ++n2) {
            uint32_t k0[4], k1[4];
            ldm4(kb + (uint32_t)(((n2 * 16 + lrow) * 40 + lcol) * 2),      k0[0], k0[1], k0[2], k0[3]);
            ldm4(kb + (uint32_t)(((n2 * 16 + lrow) * 40 + 16 + lcol) * 2), k1[0], k1[1], k1[2], k1[3]);
            mma16816(c[2 * n2],     aq0[0], aq0[1], aq0[2], aq0[3], k0[0], k0[2]);
            mma16816(c[2 * n2],     aq1[0], aq1[1], aq1[2], aq1[3], k1[0], k1[2]);
            mma16816(c[2 * n2 + 1], aq0[0], aq0[1], aq0[2], aq0[3], k0[1], k0[3]);
            mma16816(c[2 * n2 + 1], aq1[0], aq1[1], aq1[2], aq1[3], k1[1], k1[3]);
        }

        // softmax over the full 256-wide row (rows g and g+8 of this strip)
        float m0 = -1e30f, m1 = -1e30f;
#pragma unroll
        for (int nt = 0; nt < 32; ++nt) {
            m0 = fmaxf(m0, fmaxf(c[nt][0], c[nt][1]));
            m1 = fmaxf(m1, fmaxf(c[nt][2], c[nt][3]));
        }
        m0 = fmaxf(m0, __shfl_xor_sync(0xffffffffu, m0, 1));
        m0 = fmaxf(m0, __shfl_xor_sync(0xffffffffu, m0, 2));
        m1 = fmaxf(m1, __shfl_xor_sync(0xffffffffu, m1, 1));
        m1 = fmaxf(m1, __shfl_xor_sync(0xffffffffu, m1, 2));

        float l0 = 0.f, l1 = 0.f;
#pragma unroll
        for (int nt = 0; nt < 32; ++nt) {
            c[nt][0] = __expf(c[nt][0] - m0);
            c[nt][1] = __expf(c[nt][1] - m0);
            c[nt][2] = __expf(c[nt][2] - m1);
            c[nt][3] = __expf(c[nt][3] - m1);
            l0 += c[nt][0] + c[nt][1];
            l1 += c[nt][2] + c[nt][3];
        }
        l0 += __shfl_xor_sync(0xffffffffu, l0, 1);
        l0 += __shfl_xor_sync(0xffffffffu, l0, 2);
        l1 += __shfl_xor_sync(0xffffffffu, l1, 1);
        l1 += __shfl_xor_sync(0xffffffffu, l1, 2);
        const float inv0 = 1.f / l0;
        const float inv1 = 1.f / l1;

        // O = P V : P accumulators repack directly into A-fragments,
        //           V loaded with ldmatrix.trans
        float o[4][4];
#pragma unroll
        for (int on = 0; on < 4; ++on) {
            o[on][0] = 0.f; o[on][1] = 0.f; o[on][2] = 0.f; o[on][3] = 0.f;
        }
#pragma unroll
        for (int kt = 0; kt < 16; ++kt) {
            const uint32_t a0 = packh2(c[2 * kt][0],     c[2 * kt][1]);
            const uint32_t a1 = packh2(c[2 * kt][2],     c[2 * kt][3]);
            const uint32_t a2 = packh2(c[2 * kt + 1][0], c[2 * kt + 1][1]);
            const uint32_t a3 = packh2(c[2 * kt + 1][2], c[2 * kt + 1][3]);
            uint32_t v0[4], v1[4];
            ldm4t(vb + (uint32_t)(((kt * 16 + lrow) * 40 + lcol) * 2),      v0[0], v0[1], v0[2], v0[3]);
            ldm4t(vb + (uint32_t)(((kt * 16 + lrow) * 40 + 16 + lcol) * 2), v1[0], v1[1], v1[2], v1[3]);
            mma16816(o[0], a0, a1, a2, a3, v0[0], v0[1]);
            mma16816(o[1], a0, a1, a2, a3, v0[2], v0[3]);
            mma16816(o[2], a0, a1, a2, a3, v1[0], v1[1]);
            mma16816(o[3], a0, a1, a2, a3, v1[2], v1[3]);
        }

        // epilogue: normalize, fuse LePE depthwise 3x3 (cross-correlation,
        // zero-padded inside the 64x4 window), store to (B,C,H,W) layout.
#pragma unroll
        for (int on = 0; on < 4; ++on) {
#pragma unroll
            for (int oc = 0; oc < 4; ++oc) {
                const int t = r0 + g + ((oc & 2) ? 8 : 0);
                const int d = on * 8 + tg2 + (oc & 1);
                const int ih = t >> 2;
                const int jw = t & 3;
                float acc = sB[d];
#pragma unroll
                for (int ki = 0; ki < 3; ++ki) {
                    const int ii = ih + ki - 1;
                    if (ii < 0 || ii > 63) continue;
#pragma unroll
                    for (int kj = 0; kj < 3; ++kj) {
                        const int jj = jw + kj - 1;
                        if (jj < 0 || jj > 3) continue;
                        acc += sW[d * 9 + ki * 3 + kj] * sV32[(ii * 4 + jj) * 33 + d];
                    }
                }
                const float val = o[on][oc] * ((oc & 2) ? inv1 : inv0) + acc;
                out[outBase + (size_t)d * 4096 + ih * 64 + jw * 16] = val;
            }
        }
    }
}

extern "C" void kernel_launch(void* const* d_in, const int* in_sizes, int n_in,
                              void* d_out, int out_size)
{
    (void)in_sizes; (void)n_in; (void)out_size;
    const float* temp = (const float*)d_in[0];
    const float* wgt  = (const float*)d_in[1];
    const float* bias = (const float*)d_in[2];
    float* out = (float*)d_out;

    cudaFuncSetAttribute(scswmhsa_kernel,
                         cudaFuncAttributeMaxDynamicSharedMemorySize, SMEM_BYTES);
    scswmhsa_kernel<<<1024, 128, SMEM_BYTES>>>(temp, wgt, bias, out);
}

// round 2
// speedup vs baseline: 2.6989x; 2.6989x over previous
#include <cuda_runtime.h>
#include <cuda_fp16.h>
#include <stdint.h>

// 3-kernel pipeline:
//  1) gather_kernel : temp (B,3,C,64,64) fp32 -> g_qkv[win][qkv][t][d] fp16 (coalesced both sides)
//  2) attn_kernel   : per-(window,head) attention + fused LePE conv -> g_o[win][t][d] fp32
//  3) scatter_kernel: g_o -> out (B,C,H,W) (coalesced both sides)

#define SMEM_A 34816   // half[8][64][34]
#define SMEM_B 62720   // sQ/sK/sV half[256][40] + sW[288] + sB[32]
#define SMEM_C 67584   // float[8][64][33]

__device__ __half g_qkv[1024u * 3u * 256u * 32u];  // 48 MB
__device__ float  g_o[1024u * 256u * 32u];         // 32 MB

__device__ __forceinline__ void ldm4(uint32_t a, uint32_t& r0, uint32_t& r1,
                                     uint32_t& r2, uint32_t& r3) {
    asm volatile("ldmatrix.sync.aligned.m8n8.x4.shared.b16 {%0,%1,%2,%3}, [%4];"
                 : "=r"(r0), "=r"(r1), "=r"(r2), "=r"(r3) : "r"(a));
}
__device__ __forceinline__ void ldm4t(uint32_t a, uint32_t& r0, uint32_t& r1,
                                      uint32_t& r2, uint32_t& r3) {
    asm volatile("ldmatrix.sync.aligned.m8n8.x4.trans.shared.b16 {%0,%1,%2,%3}, [%4];"
                 : "=r"(r0), "=r"(r1), "=r"(r2), "=r"(r3) : "r"(a));
}
__device__ __forceinline__ void mma16816(float* c,
                                         uint32_t a0, uint32_t a1, uint32_t a2, uint32_t a3,
                                         uint32_t b0, uint32_t b1) {
    asm volatile("mma.sync.aligned.m16n8k16.row.col.f32.f16.f16.f32 "
                 "{%0,%1,%2,%3},{%4,%5,%6,%7},{%8,%9},{%0,%1,%2,%3};"
                 : "+f"(c[0]), "+f"(c[1]), "+f"(c[2]), "+f"(c[3])
                 : "r"(a0), "r"(a1), "r"(a2), "r"(a3), "r"(b0), "r"(b1));
}
__device__ __forceinline__ uint32_t packh2(float a, float b) {
    __half2 h = __floats2half2_rn(a, b);
    return *reinterpret_cast<uint32_t*>(&h);
}

// ---------------------------------------------------------------------------
// Kernel 1: gather + layout transform.  grid = 8(b)*3(p)*8(head)*8(h8) = 1536
// ---------------------------------------------------------------------------
__global__ void __launch_bounds__(256)
gather_kernel(const float* __restrict__ temp)
{
    extern __shared__ __half tileA[];  // [8 h][64 w][34 c-padded]
    const int bid = blockIdx.x, tid = threadIdx.x;
    const int h8   = bid & 7;
    const int head = (bid >> 3) & 7;
    const int bp   = bid >> 6;          // b*3 + p
    const int p    = bp % 3;
    const int b    = bp / 3;

    const size_t base = ((size_t)bp * 256 + head * 32) * 4096 + (size_t)(h8 * 8) * 64;
    const float scale = (p == 0) ? 0.17677669529663687f : 1.0f;

    // coalesced read: float4 rows along w
#pragma unroll 4
    for (int j = tid; j < 4096; j += 256) {
        const int c = j >> 7, h = (j >> 4) & 7, w4 = j & 15;
        const float4 v = *reinterpret_cast<const float4*>(
            temp + base + (size_t)c * 4096 + h * 64 + w4 * 4);
        const int sb = (h * 64 + w4 * 4) * 34 + c;
        tileA[sb]       = __float2half_rn(v.x * scale);
        tileA[sb + 34]  = __float2half_rn(v.y * scale);
        tileA[sb + 68]  = __float2half_rn(v.z * scale);
        tileA[sb + 102] = __float2half_rn(v.w * scale);
    }
    __syncthreads();

    // packed write: per token (h,w), 16 lanes write 32 halves (64B segment)
    const int wb = (b * 8 + head) * 16;
    const int d  = (tid & 15) * 2;
#pragma unroll 4
    for (int pp = tid >> 4; pp < 512; pp += 16) {
        const int h = pp >> 6, w = pp & 63;
        const int win = wb + (w & 15);
        const int t   = (h8 * 8 + h) * 4 + (w >> 4);
        const uint32_t val = *reinterpret_cast<const uint32_t*>(&tileA[(h * 64 + w) * 34 + d]);
        *reinterpret_cast<uint32_t*>(&g_qkv[(((size_t)win * 3 + p) * 256 + t) * 32 + d]) = val;
    }
}

// ---------------------------------------------------------------------------
// Kernel 2: attention + fused LePE.  grid = 1024 windows, 128 threads
// ---------------------------------------------------------------------------
__global__ void __launch_bounds__(128)
attn_kernel(const float* __restrict__ wgt, const float* __restrict__ bias)
{
    const int win  = blockIdx.x;
    const int tid  = threadIdx.x;
    const int lane = tid & 31;
    const int wid  = tid >> 5;

    extern __shared__ char smem[];
    __half* sQ = reinterpret_cast<__half*>(smem);            // [256][40]
    __half* sK = reinterpret_cast<__half*>(smem + 20480);
    __half* sV = reinterpret_cast<__half*>(smem + 40960);
    float*  sW = reinterpret_cast<float*>(smem + 61440);     // [32][9]
    float*  sB = reinterpret_cast<float*>(smem + 62592);     // [32]

    const int head  = (win >> 4) & 7;
    const int cbase = head * 32;

    for (int i = tid; i < 288; i += 128) sW[i] = wgt[cbase * 9 + i];
    if (tid < 32) sB[tid] = bias[cbase + tid];

    // coalesced uint4 loads of Q, K, V (each 256x32 halves contiguous)
    const uint4* src = reinterpret_cast<const uint4*>(g_qkv) + (size_t)win * 3072;
#pragma unroll 4
    for (int j = tid; j < 1024; j += 128) {
        const uint4 v = src[j];
        const int t = j >> 2, dd = (j & 3) * 8;
        *reinterpret_cast<uint4*>(&sQ[t * 40 + dd]) = v;
    }
#pragma unroll 4
    for (int j = tid; j < 1024; j += 128) {
        const uint4 v = src[1024 + j];
        const int t = j >> 2, dd = (j & 3) * 8;
        *reinterpret_cast<uint4*>(&sK[t * 40 + dd]) = v;
    }
#pragma unroll 4
    for (int j = tid; j < 1024; j += 128) {
        const uint4 v = src[2048 + j];
        const int t = j >> 2, dd = (j & 3) * 8;
        *reinterpret_cast<uint4*>(&sV[t * 40 + dd]) = v;
    }
    __syncthreads();

    const uint32_t qb = (uint32_t)__cvta_generic_to_shared(sQ);
    const uint32_t kb = (uint32_t)__cvta_generic_to_shared(sK);
    const uint32_t vb = (uint32_t)__cvta_generic_to_shared(sV);

    const int lrow = lane & 15;
    const int lcol = (lane >> 4) << 3;
    const int g    = lane >> 2;
    const int tg2  = (lane & 3) << 1;

    float* og = g_o + (size_t)win * 8192;

    for (int s = 0; s < 4; ++s) {
        const int r0 = (s * 4 + wid) * 16;

        uint32_t aq0[4], aq1[4];
        ldm4(qb + (uint32_t)(((r0 + lrow) * 40 + lcol) * 2),      aq0[0], aq0[1], aq0[2], aq0[3]);
        ldm4(qb + (uint32_t)(((r0 + lrow) * 40 + 16 + lcol) * 2), aq1[0], aq1[1], aq1[2], aq1[3]);

        float c[32][4];
#pragma unroll
        for (int nt = 0; nt < 32; ++nt) {
            c[nt][0] = 0.f; c[nt][1] = 0.f; c[nt][2] = 0.f; c[nt][3] = 0.f;
        }

#pragma unroll
        for (int n2 = 0; n2 < 16; ++n2) {
            uint32_t k0[4], k1[4];
            ldm4(kb + (uint32_t)(((n2 * 16 + lrow) * 40 + lcol) * 2),      k0[0], k0[1], k0[2], k0[3]);
            ldm4(kb + (uint32_t)(((n2 * 16 + lrow) * 40 + 16 + lcol) * 2), k1[0], k1[1], k1[2], k1[3]);
            mma16816(c[2 * n2],     aq0[0], aq0[1], aq0[2], aq0[3], k0[0], k0[2]);
            mma16816(c[2 * n2],     aq1[0], aq1[1], aq1[2], aq1[3], k1[0], k1[2]);
            mma16816(c[2 * n2 + 1], aq0[0], aq0[1], aq0[2], aq0[3], k0[1], k0[3]);
            mma16816(c[2 * n2 + 1], aq1[0], aq1[1], aq1[2], aq1[3], k1[1], k1[3]);
        }

        float m0 = -1e30f, m1 = -1e30f;
#pragma unroll
        for (int nt = 0; nt < 32; ++nt) {
            m0 = fmaxf(m0, fmaxf(c[nt][0], c[nt][1]));
            m1 = fmaxf(m1, fmaxf(c[nt][2], c[nt][3]));
        }
        m0 = fmaxf(m0, __shfl_xor_sync(0xffffffffu, m0, 1));
        m0 = fmaxf(m0, __shfl_xor_sync(0xffffffffu, m0, 2));
        m1 = fmaxf(m1, __shfl_xor_sync(0xffffffffu, m1, 1));
        m1 = fmaxf(m1, __shfl_xor_sync(0xffffffffu, m1, 2));

        float l0 = 0.f, l1 = 0.f;
#pragma unroll
        for (int nt = 0; nt < 32; ++nt) {
            c[nt][0] = __expf(c[nt][0] - m0);
            c[nt][1] = __expf(c[nt][1] - m0);
            c[nt][2] = __expf(c[nt][2] - m1);
            c[nt][3] = __expf(c[nt][3] - m1);
            l0 += c[nt][0] + c[nt][1];
            l1 += c[nt][2] + c[nt][3];
        }
        l0 += __shfl_xor_sync(0xffffffffu, l0, 1);
        l0 += __shfl_xor_sync(0xffffffffu, l0, 2);
        l1 += __shfl_xor_sync(0xffffffffu, l1, 1);
        l1 += __shfl_xor_sync(0xffffffffu, l1, 2);
        const float inv0 = 1.f / l0;
        const float inv1 = 1.f / l1;

        float o[4][4];
#pragma unroll
        for (int on = 0; on < 4; ++on) {
            o[on][0] = 0.f; o[on][1] = 0.f; o[on][2] = 0.f; o[on][3] = 0.f;
        }
#pragma unroll
        for (int kt = 0; kt < 16; ++kt) {
            const uint32_t a0 = packh2(c[2 * kt][0],     c[2 * kt][1]);
            const uint32_t a1 = packh2(c[2 * kt][2],     c[2 * kt][3]);
            const uint32_t a2 = packh2(c[2 * kt + 1][0], c[2 * kt + 1][1]);
            const uint32_t a3 = packh2(c[2 * kt + 1][2], c[2 * kt + 1][3]);
            uint32_t v0[4], v1[4];
            ldm4t(vb + (uint32_t)(((kt * 16 + lrow) * 40 + lcol) * 2),      v0[0], v0[1], v0[2], v0[3]);
            ldm4t(vb + (uint32_t)(((kt * 16 + lrow) * 40 + 16 + lcol) * 2), v1[0], v1[1], v1[2], v1[3]);
            mma16816(o[0], a0, a1, a2, a3, v0[0], v0[1]);
            mma16816(o[1], a0, a1, a2, a3, v0[2], v0[3]);
            mma16816(o[2], a0, a1, a2, a3, v1[0], v1[1]);
            mma16816(o[3], a0, a1, a2, a3, v1[2], v1[3]);
        }

        // epilogue: normalize + LePE conv (fp16 V) + packed float2 store to g_o
#pragma unroll
        for (int on = 0; on < 4; ++on) {
#pragma unroll
            for (int ocp = 0; ocp < 4; ocp += 2) {
                const int t  = r0 + g + ((ocp & 2) ? 8 : 0);
                const int d0 = on * 8 + tg2;
                const int ih = t >> 2;
                const int jw = t & 3;
                float a0 = sB[d0], a1 = sB[d0 + 1];
#pragma unroll
                for (int ki = 0; ki < 3; ++ki) {
                    const int ii = ih + ki - 1;
                    if (ii < 0 || ii > 63) continue;
#pragma unroll
                    for (int kj = 0; kj < 3; ++kj) {
                        const int jj = jw + kj - 1;
                        if (jj < 0 || jj > 3) continue;
                        const int vix = (ii * 4 + jj) * 40 + d0;
                        a0 += sW[d0 * 9 + ki * 3 + kj]       * __half2float(sV[vix]);
                        a1 += sW[(d0 + 1) * 9 + ki * 3 + kj] * __half2float(sV[vix + 1]);
                    }
                }
                const float inv = (ocp & 2) ? inv1 : inv0;
                float2 r;
                r.x = o[on][ocp]     * inv + a0;
                r.y = o[on][ocp + 1] * inv + a1;
                *reinterpret_cast<float2*>(&og[t * 32 + d0]) = r;
            }
        }
    }
}

// ---------------------------------------------------------------------------
// Kernel 3: scatter to (B,C,H,W).  grid = 8(b)*8(head)*8(h8) = 512
// ---------------------------------------------------------------------------
__global__ void __launch_bounds__(256)
scatter_kernel(float* __restrict__ out)
{
    extern __shared__ float tileC[];  // [8 h][64 w][33 c-padded]
    const int bid = blockIdx.x, tid = threadIdx.x;
    const int h8   = bid & 7;
    const int head = (bid >> 3) & 7;
    const int b    = bid >> 6;
    const int h0   = h8 * 8;
    const int lane = tid & 31, wid = tid >> 5;
    const int wb   = (b * 8 + head) * 16;

    // coalesced read: one token (128B) per warp-iter
    for (int pp = wid; pp < 512; pp += 8) {
        const int h = pp >> 6, w = pp & 63;
        const int win = wb + (w & 15);
        const int t   = (h0 + h) * 4 + (w >> 4);
        tileC[(h * 64 + w) * 33 + lane] = g_o[((size_t)win * 256 + t) * 32 + lane];
    }
    __syncthreads();

    // coalesced write: lanes over w
    const size_t ob = ((size_t)b * 256 + head * 32) * 4096 + (size_t)h0 * 64;
#pragma unroll 4
    for (int j = tid; j < 16384; j += 256) {
        const int w = j & 63, h = (j >> 6) & 7, c = j >> 9;
        out[ob + (size_t)c * 4096 + h * 64 + w] = tileC[(h * 64 + w) * 33 + c];
    }
}

// ---------------------------------------------------------------------------
extern "C" void kernel_launch(void* const* d_in, const int* in_sizes, int n_in,
                              void* d_out, int out_size)
{
    (void)in_sizes; (void)n_in; (void)out_size;
    const float* temp = (const float*)d_in[0];
    const float* wgt  = (const float*)d_in[1];
    const float* bias = (const float*)d_in[2];
    float* out = (float*)d_out;

    cudaFuncSetAttribute(gather_kernel,  cudaFuncAttributeMaxDynamicSharedMemorySize, SMEM_A);
    cudaFuncSetAttribute(attn_kernel,    cudaFuncAttributeMaxDynamicSharedMemorySize, SMEM_B);
    cudaFuncSetAttribute(scatter_kernel, cudaFuncAttributeMaxDynamicSharedMemorySize, SMEM_C);

    gather_kernel<<<1536, 256, SMEM_A>>>(temp);
    attn_kernel<<<1024, 128, SMEM_B>>>(wgt, bias);
    scatter_kernel<<<512, 256, SMEM_C>>>(out);
}

// round 3
// speedup vs baseline: 3.2632x; 1.2091x over previous
#include <cuda_runtime.h>
#include <cuda_fp16.h>
#include <stdint.h>

// 3-kernel pipeline:
//  1) gather_kernel : temp (B,3,C,64,64) fp32 -> g_qkv[win][qkv][t][d] fp16 (coalesced both sides)
//  2) attn_kernel   : per-(window,head) attention + fused LePE conv -> g_o[win][t][d] fp32
//                     softmax via ex2.approx.f16x2 (half MUFU traffic, exp output = PV A-frags)
//  3) scatter_kernel: g_o -> out (B,C,H,W) (coalesced both sides)

#define SMEM_A 34816   // half[8][64][34]
#define SMEM_B 62720   // sQ/sK/sV half[256][40] + sW[288] + sB[32]
#define SMEM_C 67584   // float[8][64][33]

__device__ __half g_qkv[1024u * 3u * 256u * 32u];  // 48 MB
__device__ float  g_o[1024u * 256u * 32u];         // 32 MB

__device__ __forceinline__ void ldm4(uint32_t a, uint32_t& r0, uint32_t& r1,
                                     uint32_t& r2, uint32_t& r3) {
    asm volatile("ldmatrix.sync.aligned.m8n8.x4.shared.b16 {%0,%1,%2,%3}, [%4];"
                 : "=r"(r0), "=r"(r1), "=r"(r2), "=r"(r3) : "r"(a));
}
__device__ __forceinline__ void ldm4t(uint32_t a, uint32_t& r0, uint32_t& r1,
                                      uint32_t& r2, uint32_t& r3) {
    asm volatile("ldmatrix.sync.aligned.m8n8.x4.trans.shared.b16 {%0,%1,%2,%3}, [%4];"
                 : "=r"(r0), "=r"(r1), "=r"(r2), "=r"(r3) : "r"(a));
}
__device__ __forceinline__ void mma16816(float* c,
                                         uint32_t a0, uint32_t a1, uint32_t a2, uint32_t a3,
                                         uint32_t b0, uint32_t b1) {
    asm volatile("mma.sync.aligned.m16n8k16.row.col.f32.f16.f16.f32 "
                 "{%0,%1,%2,%3},{%4,%5,%6,%7},{%8,%9},{%0,%1,%2,%3};"
                 : "+f"(c[0]), "+f"(c[1]), "+f"(c[2]), "+f"(c[3])
                 : "r"(a0), "r"(a1), "r"(a2), "r"(a3), "r"(b0), "r"(b1));
}

// ---------------------------------------------------------------------------
// Kernel 1: gather + layout transform.  grid = 8(b)*3(p)*8(head)*8(h8) = 1536
// ---------------------------------------------------------------------------
__global__ void __launch_bounds__(256)
gather_kernel(const float* __restrict__ temp)
{
    extern __shared__ __half tileA[];  // [8 h][64 w][34 c-padded]
    const int bid = blockIdx.x, tid = threadIdx.x;
    const int h8   = bid & 7;
    const int head = (bid >> 3) & 7;
    const int bp   = bid >> 6;          // b*3 + p
    const int p    = bp % 3;
    const int b    = bp / 3;

    const size_t base = ((size_t)bp * 256 + head * 32) * 4096 + (size_t)(h8 * 8) * 64;
    const float scale = (p == 0) ? 0.17677669529663687f : 1.0f;

#pragma unroll 4
    for (int j = tid; j < 4096; j += 256) {
        const int c = j >> 7, h = (j >> 4) & 7, w4 = j & 15;
        const float4 v = *reinterpret_cast<const float4*>(
            temp + base + (size_t)c * 4096 + h * 64 + w4 * 4);
        const int sb = (h * 64 + w4 * 4) * 34 + c;
        tileA[sb]       = __float2half_rn(v.x * scale);
        tileA[sb + 34]  = __float2half_rn(v.y * scale);
        tileA[sb + 68]  = __float2half_rn(v.z * scale);
        tileA[sb + 102] = __float2half_rn(v.w * scale);
    }
    __syncthreads();

    const int wb = (b * 8 + head) * 16;
    const int d  = (tid & 15) * 2;
#pragma unroll 4
    for (int pp = tid >> 4; pp < 512; pp += 16) {
        const int h = pp >> 6, w = pp & 63;
        const int win = wb + (w & 15);
        const int t   = (h8 * 8 + h) * 4 + (w >> 4);
        const uint32_t val = *reinterpret_cast<const uint32_t*>(&tileA[(h * 64 + w) * 34 + d]);
        *reinterpret_cast<uint32_t*>(&g_qkv[(((size_t)win * 3 + p) * 256 + t) * 32 + d]) = val;
    }
}

// ---------------------------------------------------------------------------
// Kernel 2: attention + fused LePE.  grid = 1024 windows, 128 threads
// ---------------------------------------------------------------------------
__global__ void __launch_bounds__(128, 3)
attn_kernel(const float* __restrict__ wgt, const float* __restrict__ bias)
{
    const int win  = blockIdx.x;
    const int tid  = threadIdx.x;
    const int lane = tid & 31;
    const int wid  = tid >> 5;

    extern __shared__ char smem[];
    __half* sQ = reinterpret_cast<__half*>(smem);            // [256][40]
    __half* sK = reinterpret_cast<__half*>(smem + 20480);
    __half* sV = reinterpret_cast<__half*>(smem + 40960);
    float*  sW = reinterpret_cast<float*>(smem + 61440);     // [32][9]
    float*  sB = reinterpret_cast<float*>(smem + 62592);     // [32]

    const int head  = (win >> 4) & 7;
    const int cbase = head * 32;

    for (int i = tid; i < 288; i += 128) sW[i] = wgt[cbase * 9 + i];
    if (tid < 32) sB[tid] = bias[cbase + tid];

    const uint4* src = reinterpret_cast<const uint4*>(g_qkv) + (size_t)win * 3072;
#pragma unroll 4
    for (int j = tid; j < 1024; j += 128) {
        const uint4 v = src[j];
        const int t = j >> 2, dd = (j & 3) * 8;
        *reinterpret_cast<uint4*>(&sQ[t * 40 + dd]) = v;
    }
#pragma unroll 4
    for (int j = tid; j < 1024; j += 128) {
        const uint4 v = src[1024 + j];
        const int t = j >> 2, dd = (j & 3) * 8;
        *reinterpret_cast<uint4*>(&sK[t * 40 + dd]) = v;
    }
#pragma unroll 4
    for (int j = tid; j < 1024; j += 128) {
        const uint4 v = src[2048 + j];
        const int t = j >> 2, dd = (j & 3) * 8;
        *reinterpret_cast<uint4*>(&sV[t * 40 + dd]) = v;
    }
    __syncthreads();

    const uint32_t qb = (uint32_t)__cvta_generic_to_shared(sQ);
    const uint32_t kb = (uint32_t)__cvta_generic_to_shared(sK);
    const uint32_t vb = (uint32_t)__cvta_generic_to_shared(sV);

    const int lrow = lane & 15;
    const int lcol = (lane >> 4) << 3;
    const int g    = lane >> 2;
    const int tg2  = (lane & 3) << 1;

    float* og = g_o + (size_t)win * 8192;

    for (int s = 0; s < 4; ++s) {
        const int r0 = (s * 4 + wid) * 16;

        uint32_t aq0[4], aq1[4];
        ldm4(qb + (uint32_t)(((r0 + lrow) * 40 + lcol) * 2),      aq0[0], aq0[1], aq0[2], aq0[3]);
        ldm4(qb + (uint32_t)(((r0 + lrow) * 40 + 16 + lcol) * 2), aq1[0], aq1[1], aq1[2], aq1[3]);

        float c[32][4];
#pragma unroll
        for (int nt = 0; nt < 32; ++nt) {
            c[nt][0] = 0.f; c[nt][1] = 0.f; c[nt][2] = 0.f; c[nt][3] = 0.f;
        }

#pragma unroll
        for (int n2 = 0; n2 < 16; ++n2) {
            uint32_t k0[4], k1[4];
            ldm4(kb + (uint32_t)(((n2 * 16 + lrow) * 40 + lcol) * 2),      k0[0], k0[1], k0[2], k0[3]);
            ldm4(kb + (uint32_t)(((n2 * 16 + lrow) * 40 + 16 + lcol) * 2), k1[0], k1[1], k1[2], k1[3]);
            mma16816(c[2 * n2],     aq0[0], aq0[1], aq0[2], aq0[3], k0[0], k0[2]);
            mma16816(c[2 * n2],     aq1[0], aq1[1], aq1[2], aq1[3], k1[0], k1[2]);
            mma16816(c[2 * n2 + 1], aq0[0], aq0[1], aq0[2], aq0[3], k0[1], k0[3]);
            mma16816(c[2 * n2 + 1], aq1[0], aq1[1], aq1[2], aq1[3], k1[1], k1[3]);
        }

        // --- softmax: half2 ex2 path ---
        float m0 = -1e30f, m1 = -1e30f;
#pragma unroll
        for (int nt = 0; nt < 32; ++nt) {
            m0 = fmaxf(m0, fmaxf(c[nt][0], c[nt][1]));
            m1 = fmaxf(m1, fmaxf(c[nt][2], c[nt][3]));
        }
        m0 = fmaxf(m0, __shfl_xor_sync(0xffffffffu, m0, 1));
        m0 = fmaxf(m0, __shfl_xor_sync(0xffffffffu, m0, 2));
        m1 = fmaxf(m1, __shfl_xor_sync(0xffffffffu, m1, 1));
        m1 = fmaxf(m1, __shfl_xor_sync(0xffffffffu, m1, 2));

        const float L2E = 1.4426950408889634f;
        const float mb0 = m0 * L2E;
        const float mb1 = m1 * L2E;

        // exp2 args in fp32 (one FFMA each), pack to f16x2, one MUFU per pair.
        // Results overwrite c[nt][0..1] as raw half2 bits (the PV A-fragments).
#pragma unroll
        for (int nt = 0; nt < 32; ++nt) {
            const float a00 = fmaf(c[nt][0], L2E, -mb0);
            const float a01 = fmaf(c[nt][1], L2E, -mb0);
            const float a10 = fmaf(c[nt][2], L2E, -mb1);
            const float a11 = fmaf(c[nt][3], L2E, -mb1);
            uint32_t p0, p1;
            asm("cvt.rn.f16x2.f32 %0, %1, %2;" : "=r"(p0) : "f"(a01), "f"(a00));
            asm("cvt.rn.f16x2.f32 %0, %1, %2;" : "=r"(p1) : "f"(a11), "f"(a10));
            asm("ex2.approx.f16x2 %0, %1;" : "=r"(p0) : "r"(p0));
            asm("ex2.approx.f16x2 %0, %1;" : "=r"(p1) : "r"(p1));
            c[nt][0] = __uint_as_float(p0);
            c[nt][1] = __uint_as_float(p1);
        }

        // row sums: one HADD2 level (pair sums <= 2, ulp 2^-11*2 -> negligible),
        // then fp32 accumulation.
        float l0 = 0.f, l1 = 0.f;
#pragma unroll
        for (int nt = 0; nt < 32; nt += 2) {
            const __half2 s0 = __hadd2(*reinterpret_cast<const __half2*>(&c[nt][0]),
                                       *reinterpret_cast<const __half2*>(&c[nt + 1][0]));
            const __half2 s1 = __hadd2(*reinterpret_cast<const __half2*>(&c[nt][1]),
                                       *reinterpret_cast<const __half2*>(&c[nt + 1][1]));
            const float2 f0 = __half22float2(s0);
            const float2 f1 = __half22float2(s1);
            l0 += f0.x + f0.y;
            l1 += f1.x + f1.y;
        }
        l0 += __shfl_xor_sync(0xffffffffu, l0, 1);
        l0 += __shfl_xor_sync(0xffffffffu, l0, 2);
        l1 += __shfl_xor_sync(0xffffffffu, l1, 1);
        l1 += __shfl_xor_sync(0xffffffffu, l1, 2);
        const float inv0 = 1.f / l0;
        const float inv1 = 1.f / l1;

        // --- O = P V, P fragments already packed in c[nt][0..1] ---
        float o[4][4];
#pragma unroll
        for (int on = 0; on < 4; ++on) {
            o[on][0] = 0.f; o[on][1] = 0.f; o[on][2] = 0.f; o[on][3] = 0.f;
        }
#pragma unroll
        for (int kt = 0; kt < 16; ++kt) {
            const uint32_t a0 = __float_as_uint(c[2 * kt][0]);
            const uint32_t a1 = __float_as_uint(c[2 * kt][1]);
            const uint32_t a2 = __float_as_uint(c[2 * kt + 1][0]);
            const uint32_t a3 = __float_as_uint(c[2 * kt + 1][1]);
            uint32_t v0[4], v1[4];
            ldm4t(vb + (uint32_t)(((kt * 16 + lrow) * 40 + lcol) * 2),      v0[0], v0[1], v0[2], v0[3]);
            ldm4t(vb + (uint32_t)(((kt * 16 + lrow) * 40 + 16 + lcol) * 2), v1[0], v1[1], v1[2], v1[3]);
            mma16816(o[0], a0, a1, a2, a3, v0[0], v0[1]);
            mma16816(o[1], a0, a1, a2, a3, v0[2], v0[3]);
            mma16816(o[2], a0, a1, a2, a3, v1[0], v1[1]);
            mma16816(o[3], a0, a1, a2, a3, v1[2], v1[3]);
        }

        // epilogue: normalize + LePE conv (fp16 V) + packed float2 store to g_o
#pragma unroll
        for (int on = 0; on < 4; ++on) {
#pragma unroll
            for (int ocp = 0; ocp < 4; ocp += 2) {
                const int t  = r0 + g + ((ocp & 2) ? 8 : 0);
                const int d0 = on * 8 + tg2;
                const int ih = t >> 2;
                const int jw = t & 3;
                float a0 = sB[d0], a1 = sB[d0 + 1];
#pragma unroll
                for (int ki = 0; ki < 3; ++ki) {
                    const int ii = ih + ki - 1;
                    if (ii < 0 || ii > 63) continue;
#pragma unroll
                    for (int kj = 0; kj < 3; ++kj) {
                        const int jj = jw + kj - 1;
                        if (jj < 0 || jj > 3) continue;
                        const int vix = (ii * 4 + jj) * 40 + d0;
                        a0 += sW[d0 * 9 + ki * 3 + kj]       * __half2float(sV[vix]);
                        a1 += sW[(d0 + 1) * 9 + ki * 3 + kj] * __half2float(sV[vix + 1]);
                    }
                }
                const float inv = (ocp & 2) ? inv1 : inv0;
                float2 r;
                r.x = o[on][ocp]     * inv + a0;
                r.y = o[on][ocp + 1] * inv + a1;
                *reinterpret_cast<float2*>(&og[t * 32 + d0]) = r;
            }
        }
    }
}

// ---------------------------------------------------------------------------
// Kernel 3: scatter to (B,C,H,W).  grid = 8(b)*8(head)*8(h8) = 512
// ---------------------------------------------------------------------------
__global__ void __launch_bounds__(256)
scatter_kernel(float* __restrict__ out)
{
    extern __shared__ float tileC[];  // [8 h][64 w][33 c-padded]
    const int bid = blockIdx.x, tid = threadIdx.x;
    const int h8   = bid & 7;
    const int head = (bid >> 3) & 7;
    const int b    = bid >> 6;
    const int h0   = h8 * 8;
    const int lane = tid & 31, wid = tid >> 5;
    const int wb   = (b * 8 + head) * 16;

    for (int pp = wid; pp < 512; pp += 8) {
        const int h = pp >> 6, w = pp & 63;
        const int win = wb + (w & 15);
        const int t   = (h0 + h) * 4 + (w >> 4);
        tileC[(h * 64 + w) * 33 + lane] = g_o[((size_t)win * 256 + t) * 32 + lane];
    }
    __syncthreads();

    const size_t ob = ((size_t)b * 256 + head * 32) * 4096 + (size_t)h0 * 64;
#pragma unroll 4
    for (int j = tid; j < 16384; j += 256) {
        const int w = j & 63, h = (j >> 6) & 7, c = j >> 9;
        out[ob + (size_t)c * 4096 + h * 64 + w] = tileC[(h * 64 + w) * 33 + c];
    }
}

// ---------------------------------------------------------------------------
extern "C" void kernel_launch(void* const* d_in, const int* in_sizes, int n_in,
                              void* d_out, int out_size)
{
    (void)in_sizes; (void)n_in; (void)out_size;
    const float* temp = (const float*)d_in[0];
    const float* wgt  = (const float*)d_in[1];
    const float* bias = (const float*)d_in[2];
    float* out = (float*)d_out;

    cudaFuncSetAttribute(gather_kernel,  cudaFuncAttributeMaxDynamicSharedMemorySize, SMEM_A);
    cudaFuncSetAttribute(attn_kernel,    cudaFuncAttributeMaxDynamicSharedMemorySize, SMEM_B);
    cudaFuncSetAttribute(scatter_kernel, cudaFuncAttributeMaxDynamicSharedMemorySize, SMEM_C);

    gather_kernel<<<1536, 256, SMEM_A>>>(temp);
    attn_kernel<<<1024, 128, SMEM_B>>>(wgt, bias);
    scatter_kernel<<<512, 256, SMEM_C>>>(out);
}

// round 4
// speedup vs baseline: 4.0893x; 1.2532x over previous
#include <cuda_runtime.h>
#include <cuda_fp16.h>
#include <stdint.h>

// 3-kernel pipeline:
//  1) gather_kernel : temp fp32 -> g_qkv[win][qkv][t][d] fp16; Q pre-scaled by SCALE*log2e
//  2) attn_kernel   : streaming no-max softmax attention + fused LePE -> g_o16 fp16
//  3) scatter_kernel: g_o16 -> out (B,C,H,W)

#define SMEM_A 34816   // half[8][64][34]
#define SMEM_B 42240   // sK/sV half[256][40] + sW[288] + sB[32]
#define SMEM_C 67584   // float[8][64][33]

__device__ __half g_qkv[1024u * 3u * 256u * 32u];  // 48 MB
__device__ __half g_o16[1024u * 256u * 32u];       // 16 MB

__device__ __forceinline__ void ldm4(uint32_t a, uint32_t& r0, uint32_t& r1,
                                     uint32_t& r2, uint32_t& r3) {
    asm volatile("ldmatrix.sync.aligned.m8n8.x4.shared.b16 {%0,%1,%2,%3}, [%4];"
                 : "=r"(r0), "=r"(r1), "=r"(r2), "=r"(r3) : "r"(a));
}
__device__ __forceinline__ void ldm4t(uint32_t a, uint32_t& r0, uint32_t& r1,
                                      uint32_t& r2, uint32_t& r3) {
    asm volatile("ldmatrix.sync.aligned.m8n8.x4.trans.shared.b16 {%0,%1,%2,%3}, [%4];"
                 : "=r"(r0), "=r"(r1), "=r"(r2), "=r"(r3) : "r"(a));
}
__device__ __forceinline__ void mma16816(float* c,
                                         uint32_t a0, uint32_t a1, uint32_t a2, uint32_t a3,
                                         uint32_t b0, uint32_t b1) {
    asm volatile("mma.sync.aligned.m16n8k16.row.col.f32.f16.f16.f32 "
                 "{%0,%1,%2,%3},{%4,%5,%6,%7},{%8,%9},{%0,%1,%2,%3};"
                 : "+f"(c[0]), "+f"(c[1]), "+f"(c[2]), "+f"(c[3])
                 : "r"(a0), "r"(a1), "r"(a2), "r"(a3), "r"(b0), "r"(b1));
}
__device__ __forceinline__ uint32_t cvt_ex2(float hi, float lo) {
    uint32_t p;
    asm("cvt.rn.f16x2.f32 %0, %1, %2;" : "=r"(p) : "f"(hi), "f"(lo));
    asm("ex2.approx.f16x2 %0, %1;" : "=r"(p) : "r"(p));
    return p;
}

// ---------------------------------------------------------------------------
// Kernel 1: gather + layout transform.  grid = 8(b)*3(p)*8(head)*8(h8) = 1536
// ---------------------------------------------------------------------------
__global__ void __launch_bounds__(256)
gather_kernel(const float* __restrict__ temp)
{
    extern __shared__ __half tileA[];  // [8 h][64 w][34 c-padded]
    const int bid = blockIdx.x, tid = threadIdx.x;
    const int h8   = bid & 7;
    const int head = (bid >> 3) & 7;
    const int bp   = bid >> 6;          // b*3 + p
    const int p    = bp % 3;
    const int b    = bp / 3;

    const size_t base = ((size_t)bp * 256 + head * 32) * 4096 + (size_t)(h8 * 8) * 64;
    // Q carries SCALE * log2(e) so QK^T lands directly in the exp2 domain
    const float scale = (p == 0) ? (0.17677669529663687f * 1.4426950408889634f) : 1.0f;

#pragma unroll 4
    for (int j = tid; j < 4096; j += 256) {
        const int c = j >> 7, h = (j >> 4) & 7, w4 = j & 15;
        const float4 v = *reinterpret_cast<const float4*>(
            temp + base + (size_t)c * 4096 + h * 64 + w4 * 4);
        const int sb = (h * 64 + w4 * 4) * 34 + c;
        tileA[sb]       = __float2half_rn(v.x * scale);
        tileA[sb + 34]  = __float2half_rn(v.y * scale);
        tileA[sb + 68]  = __float2half_rn(v.z * scale);
        tileA[sb + 102] = __float2half_rn(v.w * scale);
    }
    __syncthreads();

    const int wb = (b * 8 + head) * 16;
    const int d  = (tid & 15) * 2;
#pragma unroll 4
    for (int pp = tid >> 4; pp < 512; pp += 16) {
        const int h = pp >> 6, w = pp & 63;
        const int win = wb + (w & 15);
        const int t   = (h8 * 8 + h) * 4 + (w >> 4);
        const uint32_t val = *reinterpret_cast<const uint32_t*>(&tileA[(h * 64 + w) * 34 + d]);
        *reinterpret_cast<uint32_t*>(&g_qkv[(((size_t)win * 3 + p) * 256 + t) * 32 + d]) = val;
    }
}

// ---------------------------------------------------------------------------
// Kernel 2: streaming attention + fused LePE.  grid = 1024 windows, 128 thr
// ---------------------------------------------------------------------------
__global__ void __launch_bounds__(128, 4)
attn_kernel(const float* __restrict__ wgt, const float* __restrict__ bias)
{
    const int win  = blockIdx.x;
    const int tid  = threadIdx.x;
    const int lane = tid & 31;
    const int wid  = tid >> 5;

    extern __shared__ char smem[];
    __half* sK = reinterpret_cast<__half*>(smem);            // [256][40]
    __half* sV = reinterpret_cast<__half*>(smem + 20480);    // [256][40]
    float*  sW = reinterpret_cast<float*>(smem + 40960);     // [32][9]
    float*  sB = reinterpret_cast<float*>(smem + 42112);     // [32]

    const int head  = (win >> 4) & 7;
    const int cbase = head * 32;

    for (int i = tid; i < 288; i += 128) sW[i] = wgt[cbase * 9 + i];
    if (tid < 32) sB[tid] = bias[cbase + tid];

    const uint4* src = reinterpret_cast<const uint4*>(g_qkv) + (size_t)win * 3072;

    // phase 1: Q staged into sK region; V into sV
#pragma unroll 4
    for (int j = tid; j < 1024; j += 128) {
        const int t = j >> 2, dd = (j & 3) * 8;
        *reinterpret_cast<uint4*>(&sK[t * 40 + dd]) = src[j];          // Q
        *reinterpret_cast<uint4*>(&sV[t * 40 + dd]) = src[2048 + j];   // V
    }
    __syncthreads();

    const uint32_t kb = (uint32_t)__cvta_generic_to_shared(sK);
    const uint32_t vb = (uint32_t)__cvta_generic_to_shared(sV);

    const int lrow = lane & 15;
    const int lcol = (lane >> 4) << 3;
    const int g    = lane >> 2;
    const int tg2  = (lane & 3) << 1;

    // per-warp Q fragments for all 4 strips (then sK is recycled for K)
    uint32_t qf[4][8];
#pragma unroll
    for (int s = 0; s < 4; ++s) {
        const int r0 = (s * 4 + wid) * 16;
        ldm4(kb + (uint32_t)(((r0 + lrow) * 40 + lcol) * 2),
             qf[s][0], qf[s][1], qf[s][2], qf[s][3]);
        ldm4(kb + (uint32_t)(((r0 + lrow) * 40 + 16 + lcol) * 2),
             qf[s][4], qf[s][5], qf[s][6], qf[s][7]);
    }
    __syncthreads();

    // phase 2: K overwrites the Q staging area
#pragma unroll 4
    for (int j = tid; j < 1024; j += 128) {
        const int t = j >> 2, dd = (j & 3) * 8;
        *reinterpret_cast<uint4*>(&sK[t * 40 + dd]) = src[1024 + j];
    }
    __syncthreads();

    __half* og16 = g_o16 + (size_t)win * 8192;

#pragma unroll
    for (int s = 0; s < 4; ++s) {
        const int r0 = (s * 4 + wid) * 16;

        float o[4][4];
#pragma unroll
        for (int on = 0; on < 4; ++on) {
            o[on][0] = 0.f; o[on][1] = 0.f; o[on][2] = 0.f; o[on][3] = 0.f;
        }
        float l0 = 0.f, l1 = 0.f;

        // streaming loop over 16-key chunks: QK -> exp2 -> sum -> PV
#pragma unroll
        for (int kt = 0; kt < 16; ++kt) {
            uint32_t k0[4], k1[4];
            ldm4(kb + (uint32_t)(((kt * 16 + lrow) * 40 + lcol) * 2),
                 k0[0], k0[1], k0[2], k0[3]);
            ldm4(kb + (uint32_t)(((kt * 16 + lrow) * 40 + 16 + lcol) * 2),
                 k1[0], k1[1], k1[2], k1[3]);

            float c0[4] = {0.f, 0.f, 0.f, 0.f};   // key tile 2kt   (cols 0..7)
            float c1[4] = {0.f, 0.f, 0.f, 0.f};   // key tile 2kt+1 (cols 8..15)
            mma16816(c0, qf[s][0], qf[s][1], qf[s][2], qf[s][3], k0[0], k0[2]);
            mma16816(c0, qf[s][4], qf[s][5], qf[s][6], qf[s][7], k1[0], k1[2]);
            mma16816(c1, qf[s][0], qf[s][1], qf[s][2], qf[s][3], k0[1], k0[3]);
            mma16816(c1, qf[s][4], qf[s][5], qf[s][6], qf[s][7], k1[1], k1[3]);

            // S already in log2 domain (scale folded into Q); no max needed
            const uint32_t p0 = cvt_ex2(c0[1], c0[0]);  // row g,   keys lo
            const uint32_t p1 = cvt_ex2(c0[3], c0[2]);  // row g+8, keys lo
            const uint32_t p2 = cvt_ex2(c1[1], c1[0]);  // row g,   keys hi
            const uint32_t p3 = cvt_ex2(c1[3], c1[2]);  // row g+8, keys hi

            const __half2 h0 = __hadd2(*reinterpret_cast<const __half2*>(&p0),
                                       *reinterpret_cast<const __half2*>(&p2));
            const __half2 h1 = __hadd2(*reinterpret_cast<const __half2*>(&p1),
                                       *reinterpret_cast<const __half2*>(&p3));
            const float2 f0 = __half22float2(h0);
            const float2 f1 = __half22float2(h1);
            l0 += f0.x + f0.y;
            l1 += f1.x + f1.y;

            uint32_t v0[4], v1[4];
            ldm4t(vb + (uint32_t)(((kt * 16 + lrow) * 40 + lcol) * 2),
                  v0[0], v0[1], v0[2], v0[3]);
            ldm4t(vb + (uint32_t)(((kt * 16 + lrow) * 40 + 16 + lcol) * 2),
                  v1[0], v1[1], v1[2], v1[3]);
            mma16816(o[0], p0, p1, p2, p3, v0[0], v0[1]);
            mma16816(o[1], p0, p1, p2, p3, v0[2], v0[3]);
            mma16816(o[2], p0, p1, p2, p3, v1[0], v1[1]);
            mma16816(o[3], p0, p1, p2, p3, v1[2], v1[3]);
        }

        l0 += __shfl_xor_sync(0xffffffffu, l0, 1);
        l0 += __shfl_xor_sync(0xffffffffu, l0, 2);
        l1 += __shfl_xor_sync(0xffffffffu, l1, 1);
        l1 += __shfl_xor_sync(0xffffffffu, l1, 2);
        const float inv0 = 1.f / l0;
        const float inv1 = 1.f / l1;

        // epilogue: normalize + LePE conv (fp16 V) + half2 store to g_o16
#pragma unroll
        for (int on = 0; on < 4; ++on) {
#pragma unroll
            for (int ocp = 0; ocp < 4; ocp += 2) {
                const int t  = r0 + g + ((ocp & 2) ? 8 : 0);
                const int d0 = on * 8 + tg2;
                const int ih = t >> 2;
                const int jw = t & 3;
                float a0 = sB[d0], a1 = sB[d0 + 1];
#pragma unroll
                for (int ki = 0; ki < 3; ++ki) {
                    const int ii = ih + ki - 1;
                    if (ii < 0 || ii > 63) continue;
#pragma unroll
                    for (int kj = 0; kj < 3; ++kj) {
                        const int jj = jw + kj - 1;
                        if (jj < 0 || jj > 3) continue;
                        const int vix = (ii * 4 + jj) * 40 + d0;
                        a0 += sW[d0 * 9 + ki * 3 + kj]       * __half2float(sV[vix]);
                        a1 += sW[(d0 + 1) * 9 + ki * 3 + kj] * __half2float(sV[vix + 1]);
                    }
                }
                const float inv = (ocp & 2) ? inv1 : inv0;
                const __half2 r = __floats2half2_rn(o[on][ocp] * inv + a0,
                                                    o[on][ocp + 1] * inv + a1);
                *reinterpret_cast<__half2*>(&og16[t * 32 + d0]) = r;
            }
        }
    }
}

// ---------------------------------------------------------------------------
// Kernel 3: scatter to (B,C,H,W).  grid = 8(b)*8(head)*8(h8) = 512
// ---------------------------------------------------------------------------
__global__ void __launch_bounds__(256)
scatter_kernel(float* __restrict__ out)
{
    extern __shared__ float tileC[];  // [8 h][64 w][33 c-padded]
    const int bid = blockIdx.x, tid = threadIdx.x;
    const int h8   = bid & 7;
    const int head = (bid >> 3) & 7;
    const int b    = bid >> 6;
    const int h0   = h8 * 8;
    const int lane = tid & 31, wid = tid >> 5;
    const int wb   = (b * 8 + head) * 16;
    const int d0   = (lane & 15) * 2;

    // 2 tokens per warp-iter; 16 lanes x half2 = 64B per token
    for (int pp = wid; pp < 256; pp += 8) {
        const int p2 = pp * 2 + (lane >> 4);
        const int h = p2 >> 6, w = p2 & 63;
        const int win = wb + (w & 15);
        const int t   = (h0 + h) * 4 + (w >> 4);
        const __half2 v = *reinterpret_cast<const __half2*>(
            &g_o16[((size_t)win * 256 + t) * 32 + d0]);
        const float2 f = __half22float2(v);
        tileC[(h * 64 + w) * 33 + d0]     = f.x;
        tileC[(h * 64 + w) * 33 + d0 + 1] = f.y;
    }
    __syncthreads();

    const size_t ob = ((size_t)b * 256 + head * 32) * 4096 + (size_t)h0 * 64;
#pragma unroll 4
    for (int j = tid; j < 16384; j += 256) {
        const int w = j & 63, h = (j >> 6) & 7, c = j >> 9;
        out[ob + (size_t)c * 4096 + h * 64 + w] = tileC[(h * 64 + w) * 33 + c];
    }
}

// ---------------------------------------------------------------------------
extern "C" void kernel_launch(void* const* d_in, const int* in_sizes, int n_in,
                              void* d_out, int out_size)
{
    (void)in_sizes; (void)n_in; (void)out_size;
    const float* temp = (const float*)d_in[0];
    const float* wgt  = (const float*)d_in[1];
    const float* bias = (const float*)d_in[2];
    float* out = (float*)d_out;

    cudaFuncSetAttribute(gather_kernel,  cudaFuncAttributeMaxDynamicSharedMemorySize, SMEM_A);
    cudaFuncSetAttribute(attn_kernel,    cudaFuncAttributeMaxDynamicSharedMemorySize, SMEM_B);
    cudaFuncSetAttribute(scatter_kernel, cudaFuncAttributeMaxDynamicSharedMemorySize, SMEM_C);

    gather_kernel<<<1536, 256, SMEM_A>>>(temp);
    attn_kernel<<<1024, 128, SMEM_B>>>(wgt, bias);
    scatter_kernel<<<512, 256, SMEM_C>>>(out);
}

// round 5
// speedup vs baseline: 4.4975x; 1.0998x over previous
#include <cuda_runtime.h>
#include <cuda_fp16.h>
#include <stdint.h>

// 3-kernel pipeline:
//  1) gather_kernel : temp fp32 -> g_qkv[win][qkv][t][d] fp16; Q pre-scaled by SCALE*log2e
//  2) attn_kernel   : streaming no-max softmax attention + fused LePE -> g_o16 fp16
//                     strips paired so each K/V ldmatrix feeds 2 strips (LDS /2)
//  3) scatter_kernel: g_o16 -> out (B,C,H,W), fp16 transpose tile

#define SMEM_A 38912   // half[8][64][38]
#define SMEM_B 42240   // sK/sV half[256][40] + sW[288] + sB[32]
#define SMEM_C 38912   // half[8][64][38]

__device__ __half g_qkv[1024u * 3u * 256u * 32u];  // 48 MB
__device__ __half g_o16[1024u * 256u * 32u];       // 16 MB

__device__ __forceinline__ void ldm4(uint32_t a, uint32_t& r0, uint32_t& r1,
                                     uint32_t& r2, uint32_t& r3) {
    asm volatile("ldmatrix.sync.aligned.m8n8.x4.shared.b16 {%0,%1,%2,%3}, [%4];"
                 : "=r"(r0), "=r"(r1), "=r"(r2), "=r"(r3) : "r"(a));
}
__device__ __forceinline__ void ldm4t(uint32_t a, uint32_t& r0, uint32_t& r1,
                                      uint32_t& r2, uint32_t& r3) {
    asm volatile("ldmatrix.sync.aligned.m8n8.x4.trans.shared.b16 {%0,%1,%2,%3}, [%4];"
                 : "=r"(r0), "=r"(r1), "=r"(r2), "=r"(r3) : "r"(a));
}
__device__ __forceinline__ void mma16816(float* c,
                                         uint32_t a0, uint32_t a1, uint32_t a2, uint32_t a3,
                                         uint32_t b0, uint32_t b1) {
    asm volatile("mma.sync.aligned.m16n8k16.row.col.f32.f16.f16.f32 "
                 "{%0,%1,%2,%3},{%4,%5,%6,%7},{%8,%9},{%0,%1,%2,%3};"
                 : "+f"(c[0]), "+f"(c[1]), "+f"(c[2]), "+f"(c[3])
                 : "r"(a0), "r"(a1), "r"(a2), "r"(a3), "r"(b0), "r"(b1));
}
__device__ __forceinline__ uint32_t cvt_ex2(float hi, float lo) {
    uint32_t p;
    asm("cvt.rn.f16x2.f32 %0, %1, %2;" : "=r"(p) : "f"(hi), "f"(lo));
    asm("ex2.approx.f16x2 %0, %1;" : "=r"(p) : "r"(p));
    return p;
}

// ---------------------------------------------------------------------------
// Kernel 1: gather + layout transform.  grid = 8(b)*3(p)*8(head)*8(h8) = 1536
// ---------------------------------------------------------------------------
__global__ void __launch_bounds__(256)
gather_kernel(const float* __restrict__ temp)
{
    extern __shared__ __half tileA[];  // [8 h][64 w][38 c-padded]
    const int bid = blockIdx.x, tid = threadIdx.x;
    const int h8   = bid & 7;
    const int head = (bid >> 3) & 7;
    const int bp   = bid >> 6;          // b*3 + p
    const int p    = bp % 3;
    const int b    = bp / 3;

    const size_t base = ((size_t)bp * 256 + head * 32) * 4096 + (size_t)(h8 * 8) * 64;
    // Q carries SCALE * log2(e) so QK^T lands directly in the exp2 domain
    const float scale = (p == 0) ? (0.17677669529663687f * 1.4426950408889634f) : 1.0f;

    // 2 channels per thread -> half2 packed STS.32
#pragma unroll 4
    for (int j = tid; j < 2048; j += 256) {
        const int w4 = j & 15, h = (j >> 4) & 7, c2 = j >> 7;
        const int c = c2 * 2;
        const float4 va = *reinterpret_cast<const float4*>(
            temp + base + (size_t)c * 4096 + h * 64 + w4 * 4);
        const float4 vb = *reinterpret_cast<const float4*>(
            temp + base + (size_t)(c + 1) * 4096 + h * 64 + w4 * 4);
        const int sb = (h * 64 + w4 * 4) * 38 + c;
        *reinterpret_cast<__half2*>(&tileA[sb])           = __floats2half2_rn(va.x * scale, vb.x * scale);
        *reinterpret_cast<__half2*>(&tileA[sb + 38])      = __floats2half2_rn(va.y * scale, vb.y * scale);
        *reinterpret_cast<__half2*>(&tileA[sb + 76])      = __floats2half2_rn(va.z * scale, vb.z * scale);
        *reinterpret_cast<__half2*>(&tileA[sb + 114])     = __floats2half2_rn(va.w * scale, vb.w * scale);
    }
    __syncthreads();

    const int wb = (b * 8 + head) * 16;
    const int d  = (tid & 15) * 2;
#pragma unroll 4
    for (int pp = tid >> 4; pp < 512; pp += 16) {
        const int h = pp >> 6, w = pp & 63;
        const int win = wb + (w & 15);
        const int t   = (h8 * 8 + h) * 4 + (w >> 4);
        const uint32_t val = *reinterpret_cast<const uint32_t*>(&tileA[(h * 64 + w) * 38 + d]);
        *reinterpret_cast<uint32_t*>(&g_qkv[(((size_t)win * 3 + p) * 256 + t) * 32 + d]) = val;
    }
}

// ---------------------------------------------------------------------------
// Kernel 2: streaming attention + fused LePE.  grid = 1024 windows, 128 thr
// ---------------------------------------------------------------------------
__global__ void __launch_bounds__(128, 4)
attn_kernel(const float* __restrict__ wgt, const float* __restrict__ bias)
{
    const int win  = blockIdx.x;
    const int tid  = threadIdx.x;
    const int lane = tid & 31;
    const int wid  = tid >> 5;

    extern __shared__ char smem[];
    __half* sK = reinterpret_cast<__half*>(smem);            // [256][40]
    __half* sV = reinterpret_cast<__half*>(smem + 20480);    // [256][40]
    float*  sW = reinterpret_cast<float*>(smem + 40960);     // [32][9]
    float*  sB = reinterpret_cast<float*>(smem + 42112);     // [32]

    const int head  = (win >> 4) & 7;
    const int cbase = head * 32;

    for (int i = tid; i < 288; i += 128) sW[i] = wgt[cbase * 9 + i];
    if (tid < 32) sB[tid] = bias[cbase + tid];

    const uint4* src = reinterpret_cast<const uint4*>(g_qkv) + (size_t)win * 3072;

    // phase 1: Q staged into sK region; V into sV
#pragma unroll 4
    for (int j = tid; j < 1024; j += 128) {
        const int t = j >> 2, dd = (j & 3) * 8;
        *reinterpret_cast<uint4*>(&sK[t * 40 + dd]) = src[j];          // Q
        *reinterpret_cast<uint4*>(&sV[t * 40 + dd]) = src[2048 + j];   // V
    }
    __syncthreads();

    const uint32_t kb = (uint32_t)__cvta_generic_to_shared(sK);
    const uint32_t vb = (uint32_t)__cvta_generic_to_shared(sV);

    const int lrow = lane & 15;
    const int lcol = (lane >> 4) << 3;
    const int g    = lane >> 2;
    const int tg2  = (lane & 3) << 1;

    // per-warp Q fragments for its 4 strips (rows wid*64 .. wid*64+63)
    uint32_t qf[4][8];
#pragma unroll
    for (int s = 0; s < 4; ++s) {
        const int r0 = (wid * 4 + s) * 16;
        ldm4(kb + (uint32_t)(((r0 + lrow) * 40 + lcol) * 2),
             qf[s][0], qf[s][1], qf[s][2], qf[s][3]);
        ldm4(kb + (uint32_t)(((r0 + lrow) * 40 + 16 + lcol) * 2),
             qf[s][4], qf[s][5], qf[s][6], qf[s][7]);
    }
    __syncthreads();

    // phase 2: K overwrites the Q staging area
#pragma unroll 4
    for (int j = tid; j < 1024; j += 128) {
        const int t = j >> 2, dd = (j & 3) * 8;
        *reinterpret_cast<uint4*>(&sK[t * 40 + dd]) = src[1024 + j];
    }
    __syncthreads();

    __half* og16 = g_o16 + (size_t)win * 8192;

    // strip pairs: each chunk's K/V ldmatrix feeds 2 strips
#pragma unroll
    for (int sp = 0; sp < 2; ++sp) {
        float o[2][4][4];
        float l[2][2];
#pragma unroll
        for (int u = 0; u < 2; ++u) {
            l[u][0] = 0.f; l[u][1] = 0.f;
#pragma unroll
            for (int on = 0; on < 4; ++on) {
                o[u][on][0] = 0.f; o[u][on][1] = 0.f;
                o[u][on][2] = 0.f; o[u][on][3] = 0.f;
            }
        }

#pragma unroll
        for (int kt = 0; kt < 16; ++kt) {
            uint32_t k0[4], k1[4], v0[4], v1[4];
            ldm4(kb + (uint32_t)(((kt * 16 + lrow) * 40 + lcol) * 2),
                 k0[0], k0[1], k0[2], k0[3]);
            ldm4(kb + (uint32_t)(((kt * 16 + lrow) * 40 + 16 + lcol) * 2),
                 k1[0], k1[1], k1[2], k1[3]);
            ldm4t(vb + (uint32_t)(((kt * 16 + lrow) * 40 + lcol) * 2),
                  v0[0], v0[1], v0[2], v0[3]);
            ldm4t(vb + (uint32_t)(((kt * 16 + lrow) * 40 + 16 + lcol) * 2),
                  v1[0], v1[1], v1[2], v1[3]);

#pragma unroll
            for (int u = 0; u < 2; ++u) {
                const int s = sp * 2 + u;
                float c0[4] = {0.f, 0.f, 0.f, 0.f};
                float c1[4] = {0.f, 0.f, 0.f, 0.f};
                mma16816(c0, qf[s][0], qf[s][1], qf[s][2], qf[s][3], k0[0], k0[2]);
                mma16816(c0, qf[s][4], qf[s][5], qf[s][6], qf[s][7], k1[0], k1[2]);
                mma16816(c1, qf[s][0], qf[s][1], qf[s][2], qf[s][3], k0[1], k0[3]);
                mma16816(c1, qf[s][4], qf[s][5], qf[s][6], qf[s][7], k1[1], k1[3]);

                // S already in log2 domain (scale folded into Q); no max needed
                const uint32_t p0 = cvt_ex2(c0[1], c0[0]);
                const uint32_t p1 = cvt_ex2(c0[3], c0[2]);
                const uint32_t p2 = cvt_ex2(c1[1], c1[0]);
                const uint32_t p3 = cvt_ex2(c1[3], c1[2]);

                const __half2 h0 = __hadd2(*reinterpret_cast<const __half2*>(&p0),
                                           *reinterpret_cast<const __half2*>(&p2));
                const __half2 h1 = __hadd2(*reinterpret_cast<const __half2*>(&p1),
                                           *reinterpret_cast<const __half2*>(&p3));
                const float2 f0 = __half22float2(h0);
                const float2 f1 = __half22float2(h1);
                l[u][0] += f0.x + f0.y;
                l[u][1] += f1.x + f1.y;

                mma16816(o[u][0], p0, p1, p2, p3, v0[0], v0[1]);
                mma16816(o[u][1], p0, p1, p2, p3, v0[2], v0[3]);
                mma16816(o[u][2], p0, p1, p2, p3, v1[0], v1[1]);
                mma16816(o[u][3], p0, p1, p2, p3, v1[2], v1[3]);
            }
        }

#pragma unroll
        for (int u = 0; u < 2; ++u) {
            const int r0 = (wid * 4 + sp * 2 + u) * 16;
            float l0 = l[u][0], l1 = l[u][1];
            l0 += __shfl_xor_sync(0xffffffffu, l0, 1);
            l0 += __shfl_xor_sync(0xffffffffu, l0, 2);
            l1 += __shfl_xor_sync(0xffffffffu, l1, 1);
            l1 += __shfl_xor_sync(0xffffffffu, l1, 2);
            const float inv0 = 1.f / l0;
            const float inv1 = 1.f / l1;

            // epilogue: normalize + LePE conv (fp16 V) + half2 store to g_o16
#pragma unroll
            for (int on = 0; on < 4; ++on) {
#pragma unroll
                for (int ocp = 0; ocp < 4; ocp += 2) {
                    const int t  = r0 + g + ((ocp & 2) ? 8 : 0);
                    const int d0 = on * 8 + tg2;
                    const int ih = t >> 2;
                    const int jw = t & 3;
                    float a0 = sB[d0], a1 = sB[d0 + 1];
#pragma unroll
                    for (int ki = 0; ki < 3; ++ki) {
                        const int ii = ih + ki - 1;
                        if (ii < 0 || ii > 63) continue;
#pragma unroll
                        for (int kj = 0; kj < 3; ++kj) {
                            const int jj = jw + kj - 1;
                            if (jj < 0 || jj > 3) continue;
                            const int vix = (ii * 4 + jj) * 40 + d0;
                            a0 += sW[d0 * 9 + ki * 3 + kj]       * __half2float(sV[vix]);
                            a1 += sW[(d0 + 1) * 9 + ki * 3 + kj] * __half2float(sV[vix + 1]);
                        }
                    }
                    const float inv = (ocp & 2) ? inv1 : inv0;
                    const __half2 r = __floats2half2_rn(o[u][on][ocp] * inv + a0,
                                                        o[u][on][ocp + 1] * inv + a1);
                    *reinterpret_cast<__half2*>(&og16[t * 32 + d0]) = r;
                }
            }
        }
    }
}

// ---------------------------------------------------------------------------
// Kernel 3: scatter to (B,C,H,W).  grid = 8(b)*8(head)*8(h8) = 512
// ---------------------------------------------------------------------------
__global__ void __launch_bounds__(256)
scatter_kernel(float* __restrict__ out)
{
    extern __shared__ __half tileC[];  // [8 h][64 w][38 c-padded], fp16
    const int bid = blockIdx.x, tid = threadIdx.x;
    const int h8   = bid & 7;
    const int head = (bid >> 3) & 7;
    const int b    = bid >> 6;
    const int h0   = h8 * 8;
    const int lane = tid & 31, wid = tid >> 5;
    const int wb   = (b * 8 + head) * 16;
    const int d0   = (lane & 15) * 2;

    // 2 tokens per warp-iter; 16 lanes x half2 = 64B per token
    for (int pp = wid; pp < 256; pp += 8) {
        const int p2 = pp * 2 + (lane >> 4);
        const int h = p2 >> 6, w = p2 & 63;
        const int win = wb + (w & 15);
        const int t   = (h0 + h) * 4 + (w >> 4);
        const uint32_t v = *reinterpret_cast<const uint32_t*>(
            &g_o16[((size_t)win * 256 + t) * 32 + d0]);
        *reinterpret_cast<uint32_t*>(&tileC[(h * 64 + w) * 38 + d0]) = v;
    }
    __syncthreads();

    const size_t ob = ((size_t)b * 256 + head * 32) * 4096 + (size_t)h0 * 64;
#pragma unroll 4
    for (int j = tid; j < 16384; j += 256) {
        const int w = j & 63, h = (j >> 6) & 7, c = j >> 9;
        out[ob + (size_t)c * 4096 + h * 64 + w] =
            __half2float(tileC[(h * 64 + w) * 38 + c]);
    }
}

// ---------------------------------------------------------------------------
extern "C" void kernel_launch(void* const* d_in, const int* in_sizes, int n_in,
                              void* d_out, int out_size)
{
    (void)in_sizes; (void)n_in; (void)out_size;
    const float* temp = (const float*)d_in[0];
    const float* wgt  = (const float*)d_in[1];
    const float* bias = (const float*)d_in[2];
    float* out = (float*)d_out;

    cudaFuncSetAttribute(gather_kernel,  cudaFuncAttributeMaxDynamicSharedMemorySize, SMEM_A);
    cudaFuncSetAttribute(attn_kernel,    cudaFuncAttributeMaxDynamicSharedMemorySize, SMEM_B);
    cudaFuncSetAttribute(scatter_kernel, cudaFuncAttributeMaxDynamicSharedMemorySize, SMEM_C);

    gather_kernel<<<1536, 256, SMEM_A>>>(temp);
    attn_kernel<<<1024, 128, SMEM_B>>>(wgt, bias);
    scatter_kernel<<<512, 256, SMEM_C>>>(out);
}

// round 6
// speedup vs baseline: 4.7308x; 1.0519x over previous
#include <cuda_runtime.h>
#include <cuda_fp16.h>
#include <stdint.h>

// 3-kernel pipeline:
//  1) gather_kernel : temp fp32 -> g_qkv[win][qkv][t][d] fp16; Q pre-scaled by SCALE*log2e
//                     4-h-row tiles for high occupancy / MLP
//  2) attn_kernel   : streaming no-max softmax attention + fused LePE -> g_o16 fp16
//                     cp.async staging; strip-paired mainloop
//  3) scatter_kernel: g_o16 -> out (B,C,H,W); fp16 [c][h][w] tile, STG.128

#define SMEM_A 19456   // half[4][64][38]
#define SMEM_B 42240   // sK/sV half[256][40] + sW[288] + sB[32]
#define SMEM_C 33920   // half[32][530]  (c-stride 530, h-stride 66)

__device__ __half g_qkv[1024u * 3u * 256u * 32u];  // 48 MB
__device__ __half g_o16[1024u * 256u * 32u];       // 16 MB

__device__ __forceinline__ void ldm4(uint32_t a, uint32_t& r0, uint32_t& r1,
                                     uint32_t& r2, uint32_t& r3) {
    asm volatile("ldmatrix.sync.aligned.m8n8.x4.shared.b16 {%0,%1,%2,%3}, [%4];"
                 : "=r"(r0), "=r"(r1), "=r"(r2), "=r"(r3) : "r"(a));
}
__device__ __forceinline__ void ldm4t(uint32_t a, uint32_t& r0, uint32_t& r1,
                                      uint32_t& r2, uint32_t& r3) {
    asm volatile("ldmatrix.sync.aligned.m8n8.x4.trans.shared.b16 {%0,%1,%2,%3}, [%4];"
                 : "=r"(r0), "=r"(r1), "=r"(r2), "=r"(r3) : "r"(a));
}
__device__ __forceinline__ void mma16816(float* c,
                                         uint32_t a0, uint32_t a1, uint32_t a2, uint32_t a3,
                                         uint32_t b0, uint32_t b1) {
    asm volatile("mma.sync.aligned.m16n8k16.row.col.f32.f16.f16.f32 "
                 "{%0,%1,%2,%3},{%4,%5,%6,%7},{%8,%9},{%0,%1,%2,%3};"
                 : "+f"(c[0]), "+f"(c[1]), "+f"(c[2]), "+f"(c[3])
                 : "r"(a0), "r"(a1), "r"(a2), "r"(a3), "r"(b0), "r"(b1));
}
__device__ __forceinline__ uint32_t cvt_ex2(float hi, float lo) {
    uint32_t p;
    asm("cvt.rn.f16x2.f32 %0, %1, %2;" : "=r"(p) : "f"(hi), "f"(lo));
    asm("ex2.approx.f16x2 %0, %1;" : "=r"(p) : "r"(p));
    return p;
}
__device__ __forceinline__ void cpa16(uint32_t dst, const void* src) {
    asm volatile("cp.async.ca.shared.global [%0], [%1], 16;" :: "r"(dst), "l"(src));
}

// ---------------------------------------------------------------------------
// Kernel 1: gather + layout transform.  grid = 8b*3p*8head*16h4 = 3072
// ---------------------------------------------------------------------------
__global__ void __launch_bounds__(256)
gather_kernel(const float* __restrict__ temp)
{
    extern __shared__ __half tileA[];  // [4 h][64 w][38 c-padded]
    const int bid = blockIdx.x, tid = threadIdx.x;
    const int h16  = bid & 15;
    const int head = (bid >> 4) & 7;
    const int bp   = bid >> 7;          // b*3 + p
    const int p    = bp % 3;
    const int b    = bp / 3;

    const size_t base = ((size_t)bp * 256 + head * 32) * 4096 + (size_t)(h16 * 4) * 64;
    // Q carries SCALE * log2(e) so QK^T lands directly in the exp2 domain
    const float scale = (p == 0) ? (0.17677669529663687f * 1.4426950408889634f) : 1.0f;

    // 2 channels per thread -> half2 packed STS.32
#pragma unroll
    for (int j = tid; j < 1024; j += 256) {
        const int w4 = j & 15, h = (j >> 4) & 3, c2 = j >> 6;
        const int c = c2 * 2;
        const float4 va = *reinterpret_cast<const float4*>(
            temp + base + (size_t)c * 4096 + h * 64 + w4 * 4);
        const float4 vb = *reinterpret_cast<const float4*>(
            temp + base + (size_t)(c + 1) * 4096 + h * 64 + w4 * 4);
        const int sb = (h * 64 + w4 * 4) * 38 + c;
        *reinterpret_cast<__half2*>(&tileA[sb])       = __floats2half2_rn(va.x * scale, vb.x * scale);
        *reinterpret_cast<__half2*>(&tileA[sb + 38])  = __floats2half2_rn(va.y * scale, vb.y * scale);
        *reinterpret_cast<__half2*>(&tileA[sb + 76])  = __floats2half2_rn(va.z * scale, vb.z * scale);
        *reinterpret_cast<__half2*>(&tileA[sb + 114]) = __floats2half2_rn(va.w * scale, vb.w * scale);
    }
    __syncthreads();

    const int wb = (b * 8 + head) * 16;
    const int d  = (tid & 15) * 2;
#pragma unroll
    for (int pp = tid >> 4; pp < 256; pp += 16) {
        const int h = pp >> 6, w = pp & 63;
        const int win = wb + (w & 15);
        const int t   = (h16 * 4 + h) * 4 + (w >> 4);
        const uint32_t val = *reinterpret_cast<const uint32_t*>(&tileA[(h * 64 + w) * 38 + d]);
        *reinterpret_cast<uint32_t*>(&g_qkv[(((size_t)win * 3 + p) * 256 + t) * 32 + d]) = val;
    }
}

// ---------------------------------------------------------------------------
// Kernel 2: streaming attention + fused LePE.  grid = 1024 windows, 128 thr
// ---------------------------------------------------------------------------
__global__ void __launch_bounds__(128, 4)
attn_kernel(const float* __restrict__ wgt, const float* __restrict__ bias)
{
    const int win  = blockIdx.x;
    const int tid  = threadIdx.x;
    const int lane = tid & 31;
    const int wid  = tid >> 5;

    extern __shared__ char smem[];
    __half* sK = reinterpret_cast<__half*>(smem);            // [256][40]
    __half* sV = reinterpret_cast<__half*>(smem + 20480);    // [256][40]
    float*  sW = reinterpret_cast<float*>(smem + 40960);     // [32][9]
    float*  sB = reinterpret_cast<float*>(smem + 42112);     // [32]

    const int head  = (win >> 4) & 7;
    const int cbase = head * 32;

    const uint32_t kb = (uint32_t)__cvta_generic_to_shared(sK);
    const uint32_t vb = (uint32_t)__cvta_generic_to_shared(sV);

    const uint4* src = reinterpret_cast<const uint4*>(g_qkv) + (size_t)win * 3072;

    // phase 1: Q staged into sK region; V into sV (cp.async)
#pragma unroll
    for (int j = tid; j < 1024; j += 128) {
        const int t = j >> 2, dd = (j & 3) * 8;
        const uint32_t off = (uint32_t)(t * 40 + dd) * 2;
        cpa16(kb + off, src + j);          // Q
        cpa16(vb + off, src + 2048 + j);   // V
    }
    asm volatile("cp.async.commit_group;");

    // overlap weight/bias loads with the async staging
    for (int i = tid; i < 288; i += 128) sW[i] = wgt[cbase * 9 + i];
    if (tid < 32) sB[tid] = bias[cbase + tid];

    asm volatile("cp.async.wait_group 0;");
    __syncthreads();

    const int lrow = lane & 15;
    const int lcol = (lane >> 4) << 3;
    const int g    = lane >> 2;
    const int tg2  = (lane & 3) << 1;

    // per-warp Q fragments for its 4 strips (rows wid*64 .. wid*64+63)
    uint32_t qf[4][8];
#pragma unroll
    for (int s = 0; s < 4; ++s) {
        const int r0 = (wid * 4 + s) * 16;
        ldm4(kb + (uint32_t)(((r0 + lrow) * 40 + lcol) * 2),
             qf[s][0], qf[s][1], qf[s][2], qf[s][3]);
        ldm4(kb + (uint32_t)(((r0 + lrow) * 40 + 16 + lcol) * 2),
             qf[s][4], qf[s][5], qf[s][6], qf[s][7]);
    }
    __syncthreads();

    // phase 2: K overwrites the Q staging area (cp.async)
#pragma unroll
    for (int j = tid; j < 1024; j += 128) {
        const int t = j >> 2, dd = (j & 3) * 8;
        cpa16(kb + (uint32_t)(t * 40 + dd) * 2, src + 1024 + j);
    }
    asm volatile("cp.async.commit_group;");
    asm volatile("cp.async.wait_group 0;");
    __syncthreads();

    __half* og16 = g_o16 + (size_t)win * 8192;

    // strip pairs: each chunk's K/V ldmatrix feeds 2 strips
#pragma unroll
    for (int sp = 0; sp < 2; ++sp) {
        float o[2][4][4];
        float l[2][2];
#pragma unroll
        for (int u = 0; u < 2; ++u) {
            l[u][0] = 0.f; l[u][1] = 0.f;
#pragma unroll
            for (int on = 0; on < 4; ++on) {
                o[u][on][0] = 0.f; o[u][on][1] = 0.f;
                o[u][on][2] = 0.f; o[u][on][3] = 0.f;
            }
        }

#pragma unroll
        for (int kt = 0; kt < 16; ++kt) {
            uint32_t k0[4], k1[4], v0[4], v1[4];
            ldm4(kb + (uint32_t)(((kt * 16 + lrow) * 40 + lcol) * 2),
                 k0[0], k0[1], k0[2], k0[3]);
            ldm4(kb + (uint32_t)(((kt * 16 + lrow) * 40 + 16 + lcol) * 2),
                 k1[0], k1[1], k1[2], k1[3]);
            ldm4t(vb + (uint32_t)(((kt * 16 + lrow) * 40 + lcol) * 2),
                  v0[0], v0[1], v0[2], v0[3]);
            ldm4t(vb + (uint32_t)(((kt * 16 + lrow) * 40 + 16 + lcol) * 2),
                  v1[0], v1[1], v1[2], v1[3]);

#pragma unroll
            for (int u = 0; u < 2; ++u) {
                const int s = sp * 2 + u;
                float c0[4] = {0.f, 0.f, 0.f, 0.f};
                float c1[4] = {0.f, 0.f, 0.f, 0.f};
                mma16816(c0, qf[s][0], qf[s][1], qf[s][2], qf[s][3], k0[0], k0[2]);
                mma16816(c0, qf[s][4], qf[s][5], qf[s][6], qf[s][7], k1[0], k1[2]);
                mma16816(c1, qf[s][0], qf[s][1], qf[s][2], qf[s][3], k0[1], k0[3]);
                mma16816(c1, qf[s][4], qf[s][5], qf[s][6], qf[s][7], k1[1], k1[3]);

                // S already in log2 domain (scale folded into Q); no max needed
                const uint32_t p0 = cvt_ex2(c0[1], c0[0]);
                const uint32_t p1 = cvt_ex2(c0[3], c0[2]);
                const uint32_t p2 = cvt_ex2(c1[1], c1[0]);
                const uint32_t p3 = cvt_ex2(c1[3], c1[2]);

                const __half2 h0 = __hadd2(*reinterpret_cast<const __half2*>(&p0),
                                           *reinterpret_cast<const __half2*>(&p2));
                const __half2 h1 = __hadd2(*reinterpret_cast<const __half2*>(&p1),
                                           *reinterpret_cast<const __half2*>(&p3));
                const float2 f0 = __half22float2(h0);
                const float2 f1 = __half22float2(h1);
                l[u][0] += f0.x + f0.y;
                l[u][1] += f1.x + f1.y;

                mma16816(o[u][0], p0, p1, p2, p3, v0[0], v0[1]);
                mma16816(o[u][1], p0, p1, p2, p3, v0[2], v0[3]);
                mma16816(o[u][2], p0, p1, p2, p3, v1[0], v1[1]);
                mma16816(o[u][3], p0, p1, p2, p3, v1[2], v1[3]);
            }
        }

#pragma unroll
        for (int u = 0; u < 2; ++u) {
            const int r0 = (wid * 4 + sp * 2 + u) * 16;
            float l0 = l[u][0], l1 = l[u][1];
            l0 += __shfl_xor_sync(0xffffffffu, l0, 1);
            l0 += __shfl_xor_sync(0xffffffffu, l0, 2);
            l1 += __shfl_xor_sync(0xffffffffu, l1, 1);
            l1 += __shfl_xor_sync(0xffffffffu, l1, 2);
            const float inv0 = 1.f / l0;
            const float inv1 = 1.f / l1;

            // epilogue: normalize + LePE conv (fp16 V, half2 loads) + store
#pragma unroll
            for (int on = 0; on < 4; ++on) {
#pragma unroll
                for (int ocp = 0; ocp < 4; ocp += 2) {
                    const int t  = r0 + g + ((ocp & 2) ? 8 : 0);
                    const int d0 = on * 8 + tg2;
                    const int ih = t >> 2;
                    const int jw = t & 3;
                    float a0 = sB[d0], a1 = sB[d0 + 1];
#pragma unroll
                    for (int ki = 0; ki < 3; ++ki) {
                        const int ii = ih + ki - 1;
                        if (ii < 0 || ii > 63) continue;
#pragma unroll
                        for (int kj = 0; kj < 3; ++kj) {
                            const int jj = jw + kj - 1;
                            if (jj < 0 || jj > 3) continue;
                            const __half2 vv = *reinterpret_cast<const __half2*>(
                                &sV[(ii * 4 + jj) * 40 + d0]);
                            const float2 vf = __half22float2(vv);
                            a0 += sW[d0 * 9 + ki * 3 + kj]       * vf.x;
                            a1 += sW[(d0 + 1) * 9 + ki * 3 + kj] * vf.y;
                        }
                    }
                    const float inv = (ocp & 2) ? inv1 : inv0;
                    const __half2 r = __floats2half2_rn(o[u][on][ocp] * inv + a0,
                                                        o[u][on][ocp + 1] * inv + a1);
                    *reinterpret_cast<__half2*>(&og16[t * 32 + d0]) = r;
                }
            }
        }
    }
}

// ---------------------------------------------------------------------------
// Kernel 3: scatter to (B,C,H,W).  grid = 8(b)*8(head)*8(h8) = 512
// ---------------------------------------------------------------------------
__global__ void __launch_bounds__(256)
scatter_kernel(float* __restrict__ out)
{
    extern __shared__ __half tileC[];  // [32 c][8 h][64 w]: c-stride 530, h-stride 66
    const int bid = blockIdx.x, tid = threadIdx.x;
    const int h8   = bid & 7;
    const int head = (bid >> 3) & 7;
    const int b    = bid >> 6;
    const int h0   = h8 * 8;
    const int lane = tid & 31, wid = tid >> 5;
    const int wb   = (b * 8 + head) * 16;
    const int d0   = (lane & 15) * 2;

    // phase 1: coalesced reads (64B per token per 16 lanes), transpose to [c][h][w]
    for (int pp = wid; pp < 256; pp += 8) {
        const int p2 = pp * 2 + (lane >> 4);
        const int h = p2 >> 6, w = p2 & 63;
        const int win = wb + (w & 15);
        const int t   = (h0 + h) * 4 + (w >> 4);
        const __half2 v = *reinterpret_cast<const __half2*>(
            &g_o16[((size_t)win * 256 + t) * 32 + d0]);
        tileC[d0 * 530 + h * 66 + w]       = __low2half(v);
        tileC[(d0 + 1) * 530 + h * 66 + w] = __high2half(v);
    }
    __syncthreads();

    // phase 2: vectorized write, STG.128, 512B contiguous per warp
    const size_t ob = ((size_t)b * 256 + head * 32) * 4096 + (size_t)h0 * 64;
#pragma unroll
    for (int j = tid; j < 4096; j += 256) {
        const int w4 = j & 15, h = (j >> 4) & 7, c = j >> 7;
        const int sbase = c * 530 + h * 66 + w4 * 4;
        const float2 fa = __half22float2(*reinterpret_cast<const __half2*>(&tileC[sbase]));
        const float2 fb = __half22float2(*reinterpret_cast<const __half2*>(&tileC[sbase + 2]));
        float4 r;
        r.x = fa.x; r.y = fa.y; r.z = fb.x; r.w = fb.y;
        *reinterpret_cast<float4*>(&out[ob + (size_t)c * 4096 + h * 64 + w4 * 4]) = r;
    }
}

// ---------------------------------------------------------------------------
extern "C" void kernel_launch(void* const* d_in, const int* in_sizes, int n_in,
                              void* d_out, int out_size)
{
    (void)in_sizes; (void)n_in; (void)out_size;
    const float* temp = (const float*)d_in[0];
    const float* wgt  = (const float*)d_in[1];
    const float* bias = (const float*)d_in[2];
    float* out = (float*)d_out;

    cudaFuncSetAttribute(gather_kernel,  cudaFuncAttributeMaxDynamicSharedMemorySize, SMEM_A);
    cudaFuncSetAttribute(attn_kernel,    cudaFuncAttributeMaxDynamicSharedMemorySize, SMEM_B);
    cudaFuncSetAttribute(scatter_kernel, cudaFuncAttributeMaxDynamicSharedMemorySize, SMEM_C);

    gather_kernel<<<3072, 256, SMEM_A>>>(temp);
    attn_kernel<<<1024, 128, SMEM_B>>>(wgt, bias);
    scatter_kernel<<<512, 256, SMEM_C>>>(out);
}

// round 7
// speedup vs baseline: 4.7327x; 1.0004x over previous
#include <cuda_runtime.h>
#include <cuda_fp16.h>
#include <stdint.h>

// 3-kernel pipeline:
//  1) gather_kernel : temp fp32 -> g_qkv[win][qkv][t][d] fp16; Q pre-scaled by SCALE*log2e
//  2) attn_kernel   : streaming no-max softmax attention + fused LePE -> g_o16 fp16
//                     Q frags direct from gmem; single-phase cp.async K/V;
//                     double-buffered K/V ldmatrix in mainloop
//  3) scatter_kernel: g_o16 -> out (B,C,H,W); fp16 [c][h][w] tile, STG.128

#define SMEM_A 19456   // half[4][64][38]
#define SMEM_B 42240   // sK/sV half[256][40] + sW[288] + sB[32]
#define SMEM_C 33920   // half[32][530]  (c-stride 530, h-stride 66)

__device__ __half g_qkv[1024u * 3u * 256u * 32u];  // 48 MB
__device__ __half g_o16[1024u * 256u * 32u];       // 16 MB

__device__ __forceinline__ void ldm4(uint32_t a, uint32_t& r0, uint32_t& r1,
                                     uint32_t& r2, uint32_t& r3) {
    asm volatile("ldmatrix.sync.aligned.m8n8.x4.shared.b16 {%0,%1,%2,%3}, [%4];"
                 : "=r"(r0), "=r"(r1), "=r"(r2), "=r"(r3) : "r"(a));
}
__device__ __forceinline__ void ldm4t(uint32_t a, uint32_t& r0, uint32_t& r1,
                                      uint32_t& r2, uint32_t& r3) {
    asm volatile("ldmatrix.sync.aligned.m8n8.x4.trans.shared.b16 {%0,%1,%2,%3}, [%4];"
                 : "=r"(r0), "=r"(r1), "=r"(r2), "=r"(r3) : "r"(a));
}
__device__ __forceinline__ void mma16816(float* c,
                                         uint32_t a0, uint32_t a1, uint32_t a2, uint32_t a3,
                                         uint32_t b0, uint32_t b1) {
    asm volatile("mma.sync.aligned.m16n8k16.row.col.f32.f16.f16.f32 "
                 "{%0,%1,%2,%3},{%4,%5,%6,%7},{%8,%9},{%0,%1,%2,%3};"
                 : "+f"(c[0]), "+f"(c[1]), "+f"(c[2]), "+f"(c[3])
                 : "r"(a0), "r"(a1), "r"(a2), "r"(a3), "r"(b0), "r"(b1));
}
__device__ __forceinline__ uint32_t cvt_ex2(float hi, float lo) {
    uint32_t p;
    asm("cvt.rn.f16x2.f32 %0, %1, %2;" : "=r"(p) : "f"(hi), "f"(lo));
    asm("ex2.approx.f16x2 %0, %1;" : "=r"(p) : "r"(p));
    return p;
}
__device__ __forceinline__ void cpa16(uint32_t dst, const void* src) {
    asm volatile("cp.async.ca.shared.global [%0], [%1], 16;" :: "r"(dst), "l"(src));
}
__device__ __forceinline__ uint32_t ld32h(const __half* p) {
    return *reinterpret_cast<const uint32_t*>(p);
}

// ---------------------------------------------------------------------------
// Kernel 1: gather + layout transform.  grid = 8b*3p*8head*16h4 = 3072
// ---------------------------------------------------------------------------
__global__ void __launch_bounds__(256)
gather_kernel(const float* __restrict__ temp)
{
    extern __shared__ __half tileA[];  // [4 h][64 w][38 c-padded]
    const int bid = blockIdx.x, tid = threadIdx.x;
    const int h16  = bid & 15;
    const int head = (bid >> 4) & 7;
    const int bp   = bid >> 7;          // b*3 + p
    const int p    = bp % 3;
    const int b    = bp / 3;

    const size_t base = ((size_t)bp * 256 + head * 32) * 4096 + (size_t)(h16 * 4) * 64;
    // Q carries SCALE * log2(e) so QK^T lands directly in the exp2 domain
    const float scale = (p == 0) ? (0.17677669529663687f * 1.4426950408889634f) : 1.0f;

    // 2 channels per thread -> half2 packed STS.32
#pragma unroll
    for (int j = tid; j < 1024; j += 256) {
        const int w4 = j & 15, h = (j >> 4) & 3, c2 = j >> 6;
        const int c = c2 * 2;
        const float4 va = *reinterpret_cast<const float4*>(
            temp + base + (size_t)c * 4096 + h * 64 + w4 * 4);
        const float4 vb = *reinterpret_cast<const float4*>(
            temp + base + (size_t)(c + 1) * 4096 + h * 64 + w4 * 4);
        const int sb = (h * 64 + w4 * 4) * 38 + c;
        *reinterpret_cast<__half2*>(&tileA[sb])       = __floats2half2_rn(va.x * scale, vb.x * scale);
        *reinterpret_cast<__half2*>(&tileA[sb + 38])  = __floats2half2_rn(va.y * scale, vb.y * scale);
        *reinterpret_cast<__half2*>(&tileA[sb + 76])  = __floats2half2_rn(va.z * scale, vb.z * scale);
        *reinterpret_cast<__half2*>(&tileA[sb + 114]) = __floats2half2_rn(va.w * scale, vb.w * scale);
    }
    __syncthreads();

    // phase 2: 8 lanes per token, uint2 (8B) stores
    const int wb = (b * 8 + head) * 16;
    const int d  = (tid & 7) * 4;
#pragma unroll
    for (int pp = tid >> 3; pp < 256; pp += 32) {
        const int h = pp >> 6, w = pp & 63;
        const int win = wb + (w & 15);
        const int t   = (h16 * 4 + h) * 4 + (w >> 4);
        const int sb  = (h * 64 + w) * 38 + d;
        uint2 val;
        val.x = *reinterpret_cast<const uint32_t*>(&tileA[sb]);
        val.y = *reinterpret_cast<const uint32_t*>(&tileA[sb + 2]);
        *reinterpret_cast<uint2*>(&g_qkv[(((size_t)win * 3 + p) * 256 + t) * 32 + d]) = val;
    }
}

// ---------------------------------------------------------------------------
// Kernel 2: streaming attention + fused LePE.  grid = 1024 windows, 128 thr
// ---------------------------------------------------------------------------
__global__ void __launch_bounds__(128, 4)
attn_kernel(const float* __restrict__ wgt, const float* __restrict__ bias)
{
    const int win  = blockIdx.x;
    const int tid  = threadIdx.x;
    const int lane = tid & 31;
    const int wid  = tid >> 5;

    extern __shared__ char smem[];
    __half* sK = reinterpret_cast<__half*>(smem);            // [256][40]
    __half* sV = reinterpret_cast<__half*>(smem + 20480);    // [256][40]
    float*  sW = reinterpret_cast<float*>(smem + 40960);     // [32][9]
    float*  sB = reinterpret_cast<float*>(smem + 42112);     // [32]

    const int head  = (win >> 4) & 7;
    const int cbase = head * 32;

    const uint32_t kb = (uint32_t)__cvta_generic_to_shared(sK);
    const uint32_t vb = (uint32_t)__cvta_generic_to_shared(sV);

    const __half* qkvg = g_qkv + (size_t)win * 3u * 8192u;
    const uint4* srcK = reinterpret_cast<const uint4*>(qkvg + 8192);
    const uint4* srcV = reinterpret_cast<const uint4*>(qkvg + 16384);

    // single phase: K and V staged via cp.async
#pragma unroll
    for (int j = tid; j < 1024; j += 128) {
        const int t = j >> 2, dd = (j & 3) * 8;
        const uint32_t off = (uint32_t)(t * 40 + dd) * 2;
        cpa16(kb + off, srcK + j);
        cpa16(vb + off, srcV + j);
    }
    asm volatile("cp.async.commit_group;");

    // overlap with async window: conv weights/bias + Q fragments from gmem
    for (int i = tid; i < 288; i += 128) sW[i] = wgt[cbase * 9 + i];
    if (tid < 32) sB[tid] = bias[cbase + tid];

    const int g   = lane >> 2;
    const int tg2 = (lane & 3) << 1;

    uint32_t qf[4][8];
#pragma unroll
    for (int s = 0; s < 4; ++s) {
        const int r0 = (wid * 4 + s) * 16;
        const __half* q0 = qkvg + (r0 + g) * 32 + tg2;
        const __half* q1 = qkvg + (r0 + g + 8) * 32 + tg2;
        qf[s][0] = ld32h(q0);      qf[s][1] = ld32h(q1);
        qf[s][2] = ld32h(q0 + 8);  qf[s][3] = ld32h(q1 + 8);
        qf[s][4] = ld32h(q0 + 16); qf[s][5] = ld32h(q1 + 16);
        qf[s][6] = ld32h(q0 + 24); qf[s][7] = ld32h(q1 + 24);
    }

    asm volatile("cp.async.wait_group 0;");
    __syncthreads();

    const int lrow = lane & 15;
    const int lcol = (lane >> 4) << 3;

    __half* og16 = g_o16 + (size_t)win * 8192;

    // strip pairs; K/V fragments double-buffered across chunks
#pragma unroll
    for (int sp = 0; sp < 2; ++sp) {
        float o[2][4][4];
        float l[2][2];
#pragma unroll
        for (int u = 0; u < 2; ++u) {
            l[u][0] = 0.f; l[u][1] = 0.f;
#pragma unroll
            for (int on = 0; on < 4; ++on) {
                o[u][on][0] = 0.f; o[u][on][1] = 0.f;
                o[u][on][2] = 0.f; o[u][on][3] = 0.f;
            }
        }

        uint32_t kf[2][8], vf[2][8];
        // prime chunk 0
        ldm4 (kb + (uint32_t)((lrow * 40 + lcol) * 2),        kf[0][0], kf[0][1], kf[0][2], kf[0][3]);
        ldm4 (kb + (uint32_t)((lrow * 40 + 16 + lcol) * 2),   kf[0][4], kf[0][5], kf[0][6], kf[0][7]);
        ldm4t(vb + (uint32_t)((lrow * 40 + lcol) * 2),        vf[0][0], vf[0][1], vf[0][2], vf[0][3]);
        ldm4t(vb + (uint32_t)((lrow * 40 + 16 + lcol) * 2),   vf[0][4], vf[0][5], vf[0][6], vf[0][7]);

#pragma unroll
        for (int kt = 0; kt < 16; ++kt) {
            const int cur = kt & 1;
            const int nxt = cur ^ 1;
            if (kt < 15) {
                const uint32_t rb = (uint32_t)(((kt + 1) * 16 + lrow) * 40) * 2;
                ldm4 (kb + rb + lcol * 2,        kf[nxt][0], kf[nxt][1], kf[nxt][2], kf[nxt][3]);
                ldm4 (kb + rb + (16 + lcol) * 2, kf[nxt][4], kf[nxt][5], kf[nxt][6], kf[nxt][7]);
                ldm4t(vb + rb + lcol * 2,        vf[nxt][0], vf[nxt][1], vf[nxt][2], vf[nxt][3]);
                ldm4t(vb + rb + (16 + lcol) * 2, vf[nxt][4], vf[nxt][5], vf[nxt][6], vf[nxt][7]);
            }

#pragma unroll
            for (int u = 0; u < 2; ++u) {
                const int s = sp * 2 + u;
                float c0[4] = {0.f, 0.f, 0.f, 0.f};
                float c1[4] = {0.f, 0.f, 0.f, 0.f};
                mma16816(c0, qf[s][0], qf[s][1], qf[s][2], qf[s][3], kf[cur][0], kf[cur][2]);
                mma16816(c0, qf[s][4], qf[s][5], qf[s][6], qf[s][7], kf[cur][4], kf[cur][6]);
                mma16816(c1, qf[s][0], qf[s][1], qf[s][2], qf[s][3], kf[cur][1], kf[cur][3]);
                mma16816(c1, qf[s][4], qf[s][5], qf[s][6], qf[s][7], kf[cur][5], kf[cur][7]);

                // S already in log2 domain (scale folded into Q); no max needed
                const uint32_t p0 = cvt_ex2(c0[1], c0[0]);
                const uint32_t p1 = cvt_ex2(c0[3], c0[2]);
                const uint32_t p2 = cvt_ex2(c1[1], c1[0]);
                const uint32_t p3 = cvt_ex2(c1[3], c1[2]);

                const __half2 h0 = __hadd2(*reinterpret_cast<const __half2*>(&p0),
                                           *reinterpret_cast<const __half2*>(&p2));
                const __half2 h1 = __hadd2(*reinterpret_cast<const __half2*>(&p1),
                                           *reinterpret_cast<const __half2*>(&p3));
                const float2 f0 = __half22float2(h0);
                const float2 f1 = __half22float2(h1);
                l[u][0] += f0.x + f0.y;
                l[u][1] += f1.x + f1.y;

                mma16816(o[u][0], p0, p1, p2, p3, vf[cur][0], vf[cur][1]);
                mma16816(o[u][1], p0, p1, p2, p3, vf[cur][2], vf[cur][3]);
                mma16816(o[u][2], p0, p1, p2, p3, vf[cur][4], vf[cur][5]);
                mma16816(o[u][3], p0, p1, p2, p3, vf[cur][6], vf[cur][7]);
            }
        }

#pragma unroll
        for (int u = 0; u < 2; ++u) {
            const int r0 = (wid * 4 + sp * 2 + u) * 16;
            float l0 = l[u][0], l1 = l[u][1];
            l0 += __shfl_xor_sync(0xffffffffu, l0, 1);
            l0 += __shfl_xor_sync(0xffffffffu, l0, 2);
            l1 += __shfl_xor_sync(0xffffffffu, l1, 1);
            l1 += __shfl_xor_sync(0xffffffffu, l1, 2);
            const float inv0 = 1.f / l0;
            const float inv1 = 1.f / l1;

            // epilogue: normalize + LePE conv (fp16 V, half2 loads) + store
#pragma unroll
            for (int on = 0; on < 4; ++on) {
#pragma unroll
                for (int ocp = 0; ocp < 4; ocp += 2) {
                    const int t  = r0 + g + ((ocp & 2) ? 8 : 0);
                    const int d0 = on * 8 + tg2;
                    const int ih = t >> 2;
                    const int jw = t & 3;
                    float a0 = sB[d0], a1 = sB[d0 + 1];
#pragma unroll
                    for (int ki = 0; ki < 3; ++ki) {
                        const int ii = ih + ki - 1;
                        if (ii < 0 || ii > 63) continue;
#pragma unroll
                        for (int kj = 0; kj < 3; ++kj) {
                            const int jj = jw + kj - 1;
                            if (jj < 0 || jj > 3) continue;
                            const __half2 vv = *reinterpret_cast<const __half2*>(
                                &sV[(ii * 4 + jj) * 40 + d0]);
                            const float2 vf2 = __half22float2(vv);
                            a0 += sW[d0 * 9 + ki * 3 + kj]       * vf2.x;
                            a1 += sW[(d0 + 1) * 9 + ki * 3 + kj] * vf2.y;
                        }
                    }
                    const float inv = (ocp & 2) ? inv1 : inv0;
                    const __half2 r = __floats2half2_rn(o[u][on][ocp] * inv + a0,
                                                        o[u][on][ocp + 1] * inv + a1);
                    *reinterpret_cast<__half2*>(&og16[t * 32 + d0]) = r;
                }
            }
        }
    }
}

// ---------------------------------------------------------------------------
// Kernel 3: scatter to (B,C,H,W).  grid = 8(b)*8(head)*8(h8) = 512
// ---------------------------------------------------------------------------
__global__ void __launch_bounds__(256)
scatter_kernel(float* __restrict__ out)
{
    extern __shared__ __half tileC[];  // [32 c][8 h][64 w]: c-stride 530, h-stride 66
    const int bid = blockIdx.x, tid = threadIdx.x;
    const int h8   = bid & 7;
    const int head = (bid >> 3) & 7;
    const int b    = bid >> 6;
    const int h0   = h8 * 8;
    const int lane = tid & 31, wid = tid >> 5;
    const int wb   = (b * 8 + head) * 16;
    const int d0   = (lane & 15) * 2;

    // phase 1: coalesced reads (64B per token per 16 lanes), transpose to [c][h][w]
    for (int pp = wid; pp < 256; pp += 8) {
        const int p2 = pp * 2 + (lane >> 4);
        const int h = p2 >> 6, w = p2 & 63;
        const int win = wb + (w & 15);
        const int t   = (h0 + h) * 4 + (w >> 4);
        const __half2 v = *reinterpret_cast<const __half2*>(
            &g_o16[((size_t)win * 256 + t) * 32 + d0]);
        tileC[d0 * 530 + h * 66 + w]       = __low2half(v);
        tileC[(d0 + 1) * 530 + h * 66 + w] = __high2half(v);
    }
    __syncthreads();

    // phase 2: vectorized write, STG.128, 512B contiguous per warp
    const size_t ob = ((size_t)b * 256 + head * 32) * 4096 + (size_t)h0 * 64;
#pragma unroll
    for (int j = tid; j < 4096; j += 256) {
        const int w4 = j & 15, h = (j >> 4) & 7, c = j >> 7;
        const int sbase = c * 530 + h * 66 + w4 * 4;
        const float2 fa = __half22float2(*reinterpret_cast<const __half2*>(&tileC[sbase]));
        const float2 fb = __half22float2(*reinterpret_cast<const __half2*>(&tileC[sbase + 2]));
        float4 r;
        r.x = fa.x; r.y = fa.y; r.z = fb.x; r.w = fb.y;
        *reinterpret_cast<float4*>(&out[ob + (size_t)c * 4096 + h * 64 + w4 * 4]) = r;
    }
}

// ---------------------------------------------------------------------------
extern "C" void kernel_launch(void* const* d_in, const int* in_sizes, int n_in,
                              void* d_out, int out_size)
{
    (void)in_sizes; (void)n_in; (void)out_size;
    const float* temp = (const float*)d_in[0];
    const float* wgt  = (const float*)d_in[1];
    const float* bias = (const float*)d_in[2];
    float* out = (float*)d_out;

    cudaFuncSetAttribute(gather_kernel,  cudaFuncAttributeMaxDynamicSharedMemorySize, SMEM_A);
    cudaFuncSetAttribute(attn_kernel,    cudaFuncAttributeMaxDynamicSharedMemorySize, SMEM_B);
    cudaFuncSetAttribute(scatter_kernel, cudaFuncAttributeMaxDynamicSharedMemorySize, SMEM_C);

    gather_kernel<<<3072, 256, SMEM_A>>>(temp);
    attn_kernel<<<1024, 128, SMEM_B>>>(wgt, bias);
    scatter_kernel<<<512, 256, SMEM_C>>>(out);
}